// round 1
// baseline (speedup 1.0000x reference)
#include <cuda_runtime.h>
#include <mma.h>
#include <math.h>
#include <stdint.h>

using namespace nvcuda;

// Problem constants
#define Bb    2
#define Ss    2048
#define Kn    8
#define Dd    1024
#define Pp    32
#define KPp   4
#define DFFd  4096
#define NTOK  (Bb*Ss)        // 4096 tokens
#define MQKV  (NTOK*Kn)      // 32768 rows for QKV GEMM

// ----------------------------------------------------------------------------
// Scratch (static device globals; no runtime allocation)
// ----------------------------------------------------------------------------
__device__ float g_Q[(size_t)MQKV * Dd];
__device__ float g_K[(size_t)MQKV * Dd];
__device__ float g_V[(size_t)MQKV * Dd];
__device__ float g_comb[(size_t)NTOK * Dd];
__device__ float g_h[(size_t)NTOK * DFFd];

// ----------------------------------------------------------------------------
// TF32 WMMA GEMM:  C[M,N] = A[M,K] @ B[N,K]^T + bias (+ optional exact GELU)
// Block tile 128x64, BK=32, 256 threads (8 warps as 4x2, each 32x32)
// ----------------------------------------------------------------------------
#define GBM 128
#define GBN 64
#define GBK 32
#define GLD (GBK + 4)   // 36 floats row stride (16B multiple)

__device__ __forceinline__ float gelu_exact(float v) {
    return 0.5f * v * (1.0f + erff(v * 0.70710678118654752440f));
}

__global__ __launch_bounds__(256) void gemm_tf32(
    const float* __restrict__ A, const float* __restrict__ Bw,
    const float* __restrict__ bias, float* __restrict__ C,
    int M, int N, int Kd, int act)
{
    __shared__ __align__(32) float smem[GBM * GBN];   // 8192 floats = 32KB (reused for C)
    float* As = smem;                  // [GBM][GLD] = 4608 floats
    float* Bs = smem + GBM * GLD;      // [GBN][GLD] = 2304 floats (total 6912 <= 8192)

    const int t    = threadIdx.x;
    const int warp = t >> 5;
    const int wm   = warp >> 1;        // 0..3
    const int wn   = warp & 1;         // 0..1
    const int m0   = blockIdx.y * GBM;
    const int n0   = blockIdx.x * GBN;

    wmma::fragment<wmma::accumulator, 16, 16, 8, float> acc[2][2];
    #pragma unroll
    for (int i = 0; i < 2; i++)
        #pragma unroll
        for (int j = 0; j < 2; j++)
            wmma::fill_fragment(acc[i][j], 0.0f);

    for (int k0 = 0; k0 < Kd; k0 += GBK) {
        // Cooperative loads (float4). A: 128x32 = 1024 float4, B: 64x32 = 512 float4
        #pragma unroll
        for (int i = 0; i < 4; i++) {
            int idx = t + 256 * i;
            int r = idx >> 3, c4 = idx & 7;
            float4 v = *(const float4*)(A + (size_t)(m0 + r) * Kd + k0 + c4 * 4);
            *(float4*)(As + r * GLD + c4 * 4) = v;
        }
        #pragma unroll
        for (int i = 0; i < 2; i++) {
            int idx = t + 256 * i;
            int r = idx >> 3, c4 = idx & 7;
            float4 v = *(const float4*)(Bw + (size_t)(n0 + r) * Kd + k0 + c4 * 4);
            *(float4*)(Bs + r * GLD + c4 * 4) = v;
        }
        __syncthreads();

        #pragma unroll
        for (int kk = 0; kk < GBK; kk += 8) {
            wmma::fragment<wmma::matrix_a, 16, 16, 8, wmma::precision::tf32, wmma::row_major> af[2];
            wmma::fragment<wmma::matrix_b, 16, 16, 8, wmma::precision::tf32, wmma::col_major> bf[2];
            #pragma unroll
            for (int i = 0; i < 2; i++) {
                wmma::load_matrix_sync(af[i], As + (wm * 32 + i * 16) * GLD + kk, GLD);
                #pragma unroll
                for (int e = 0; e < af[i].num_elements; e++)
                    af[i].x[e] = wmma::__float_to_tf32(af[i].x[e]);
            }
            #pragma unroll
            for (int j = 0; j < 2; j++) {
                wmma::load_matrix_sync(bf[j], Bs + (wn * 32 + j * 16) * GLD + kk, GLD);
                #pragma unroll
                for (int e = 0; e < bf[j].num_elements; e++)
                    bf[j].x[e] = wmma::__float_to_tf32(bf[j].x[e]);
            }
            #pragma unroll
            for (int i = 0; i < 2; i++)
                #pragma unroll
                for (int j = 0; j < 2; j++)
                    wmma::mma_sync(acc[i][j], af[i], bf[j], acc[i][j]);
        }
        __syncthreads();
    }

    // Epilogue: stage accumulators in smem, then bias (+gelu) and coalesced store
    float* Cs = smem;   // [GBM][GBN]
    #pragma unroll
    for (int i = 0; i < 2; i++)
        #pragma unroll
        for (int j = 0; j < 2; j++)
            wmma::store_matrix_sync(Cs + (wm * 32 + i * 16) * GBN + wn * 32 + j * 16,
                                    acc[i][j], GBN, wmma::mem_row_major);
    __syncthreads();

    #pragma unroll
    for (int i = 0; i < 8; i++) {
        int idx = t + 256 * i;
        int r = idx >> 4, c4 = idx & 15;
        float4 v = *(float4*)(Cs + r * GBN + c4 * 4);
        int n = n0 + c4 * 4;
        v.x += bias[n + 0]; v.y += bias[n + 1]; v.z += bias[n + 2]; v.w += bias[n + 3];
        if (act) {
            v.x = gelu_exact(v.x); v.y = gelu_exact(v.y);
            v.z = gelu_exact(v.z); v.w = gelu_exact(v.w);
        }
        *(float4*)(C + (size_t)(m0 + r) * N + n) = v;
    }
}

// ----------------------------------------------------------------------------
// Fused per-token kernel: K-wide self-attention, pattern scoring (factored),
// top-4 selection, final attention, aggregation, combine with x.
// One block per token, 256 threads. Everything except Q/K/V reads stays on-chip.
// ----------------------------------------------------------------------------
__global__ __launch_bounds__(256) void attn_fused(
    const float* __restrict__ Q, const float* __restrict__ Km, const float* __restrict__ V,
    const float* __restrict__ pq, const float* __restrict__ x, const float* __restrict__ ctx,
    const float* __restrict__ tw, float* __restrict__ comb)
{
    const int tok  = blockIdx.x;
    const int t    = threadIdx.x;
    const int warp = t >> 5;
    const int lane = t & 31;
    const float scale = 0.03125f;   // 1/sqrt(1024)

    __shared__ float sI[8][1028];   // interacted (padded rows)
    __shared__ float sWI[1028];     // sum_k w[k]*interacted[k][d]
    __shared__ float sCtx[1024];
    __shared__ float sA[8][8];
    __shared__ float sW[8];
    __shared__ float sNB[32], sCB[32];
    __shared__ float sSel[4][8];
    __shared__ float sTw[4];
    __shared__ int   sTi[4];
    __shared__ float sFA[8];

    const size_t base = (size_t)tok * 8 * 1024;
    const float* Qt = Q + base;
    const float* Kt = Km + base;
    const float* Vt = V + base;

    if (t < 8) sW[t] = tw[tok * 8 + t];
    #pragma unroll
    for (int r = 0; r < 4; r++) sCtx[t + 256 * r] = ctx[(size_t)tok * 1024 + t + 256 * r];

    // ---- Stage 1: attention scores + row softmax (warp i handles row i) ----
    {
        const int i = warp;
        float qreg[32];
        #pragma unroll
        for (int u = 0; u < 32; u++) qreg[u] = Qt[i * 1024 + u * 32 + lane];
        float sc[8];
        #pragma unroll
        for (int j = 0; j < 8; j++) {
            float a = 0.0f;
            #pragma unroll
            for (int u = 0; u < 32; u++) a = fmaf(qreg[u], Kt[j * 1024 + u * 32 + lane], a);
            #pragma unroll
            for (int o = 16; o > 0; o >>= 1) a += __shfl_xor_sync(0xffffffffu, a, o);
            sc[j] = a * scale;
        }
        if (lane == 0) {
            float m = sc[0];
            #pragma unroll
            for (int j = 1; j < 8; j++) m = fmaxf(m, sc[j]);
            float e[8], s = 0.0f;
            #pragma unroll
            for (int j = 0; j < 8; j++) { e[j] = expf(sc[j] - m); s += e[j]; }
            float inv = 1.0f / s;
            #pragma unroll
            for (int j = 0; j < 8; j++) sA[i][j] = e[j] * inv;
        }
    }
    __syncthreads();

    // ---- Stage 2: interacted = attn @ V; also weighted sum for neuron_based ----
    #pragma unroll
    for (int r = 0; r < 4; r++) {
        int d = t + 256 * r;
        float a[8] = {0,0,0,0,0,0,0,0};
        #pragma unroll
        for (int j = 0; j < 8; j++) {
            float v = Vt[j * 1024 + d];
            #pragma unroll
            for (int i = 0; i < 8; i++) a[i] = fmaf(sA[i][j], v, a[i]);
        }
        float wi = 0.0f;
        #pragma unroll
        for (int i = 0; i < 8; i++) { sI[i][d] = a[i]; wi = fmaf(sW[i], a[i], wi); }
        sWI[d] = wi;
    }
    __syncthreads();

    // ---- Stage 3: neuron_based + context_based (warp w owns p = 4w..4w+3) ----
    #pragma unroll
    for (int q = 0; q < 4; q++) {
        int p = warp * 4 + q;
        const float* pr = pq + (size_t)p * 1024;
        float nb = 0.0f, cb = 0.0f;
        #pragma unroll
        for (int u = 0; u < 32; u++) {
            int d = u * 32 + lane;
            float pv = pr[d];
            nb = fmaf(pv, sWI[d], nb);
            cb = fmaf(pv, sCtx[d], cb);
        }
        #pragma unroll
        for (int o = 16; o > 0; o >>= 1) {
            nb += __shfl_xor_sync(0xffffffffu, nb, o);
            cb += __shfl_xor_sync(0xffffffffu, cb, o);
        }
        if (lane == 0) { sNB[p] = nb * scale; sCB[p] = cb; }
    }
    __syncthreads();

    // ---- Stage 4: top-4 of pattern scores + softmax of the 4 (warp 0) ----
    if (warp == 0) {
        float s = 0.5f * sNB[lane] + 0.5f * sCB[lane];
        float vals[4]; int ids[4];
        #pragma unroll
        for (int r = 0; r < 4; r++) {
            float v = s; int idx = lane;
            #pragma unroll
            for (int o = 16; o > 0; o >>= 1) {
                float ov = __shfl_xor_sync(0xffffffffu, v, o);
                int   oi = __shfl_xor_sync(0xffffffffu, idx, o);
                if (ov > v || (ov == v && oi < idx)) { v = ov; idx = oi; }
            }
            vals[r] = v; ids[r] = idx;
            if (lane == idx) s = -3.4e38f;
        }
        if (lane == 0) {
            float m = fmaxf(fmaxf(vals[0], vals[1]), fmaxf(vals[2], vals[3]));
            float e0 = expf(vals[0] - m), e1 = expf(vals[1] - m);
            float e2 = expf(vals[2] - m), e3 = expf(vals[3] - m);
            float inv = 1.0f / (e0 + e1 + e2 + e3);
            sTw[0] = e0 * inv; sTw[1] = e1 * inv; sTw[2] = e2 * inv; sTw[3] = e3 * inv;
            sTi[0] = ids[0]; sTi[1] = ids[1]; sTi[2] = ids[2]; sTi[3] = ids[3];
        }
    }
    __syncthreads();

    // ---- Stage 5: nps rows for the 4 selected patterns, softmax, weight ----
    if (warp < 4) {
        int pi = sTi[warp];
        const float* pr = pq + (size_t)pi * 1024;
        float pv[32];
        #pragma unroll
        for (int u = 0; u < 32; u++) pv[u] = pr[u * 32 + lane];
        float sel[8];
        #pragma unroll
        for (int k = 0; k < 8; k++) {
            float a = 0.0f;
            #pragma unroll
            for (int u = 0; u < 32; u++) a = fmaf(pv[u], sI[k][u * 32 + lane], a);
            #pragma unroll
            for (int o = 16; o > 0; o >>= 1) a += __shfl_xor_sync(0xffffffffu, a, o);
            sel[k] = a * scale;
        }
        if (lane == 0) {
            float m = sel[0];
            #pragma unroll
            for (int k = 1; k < 8; k++) m = fmaxf(m, sel[k]);
            float e[8], sum = 0.0f;
            #pragma unroll
            for (int k = 0; k < 8; k++) { e[k] = expf(sel[k] - m); sum += e[k]; }
            float f = sTw[warp] / sum;
            #pragma unroll
            for (int k = 0; k < 8; k++) sSel[warp][k] = e[k] * f;
        }
    }
    __syncthreads();
    if (t < 8) sFA[t] = sSel[0][t] + sSel[1][t] + sSel[2][t] + sSel[3][t];
    __syncthreads();

    // ---- Stage 6: aggregated + residual -> combined ----
    float fa[8];
    #pragma unroll
    for (int k = 0; k < 8; k++) fa[k] = sFA[k];
    #pragma unroll
    for (int r = 0; r < 4; r++) {
        int d = t + 256 * r;
        float a = x[(size_t)tok * 1024 + d];
        #pragma unroll
        for (int k = 0; k < 8; k++) a = fmaf(fa[k], sI[k][d], a);
        comb[(size_t)tok * 1024 + d] = a;
    }
}

// ----------------------------------------------------------------------------
// Launch
// ----------------------------------------------------------------------------
extern "C" void kernel_launch(void* const* d_in, const int* in_sizes, int n_in,
                              void* d_out, int out_size)
{
    const float* x     = (const float*)d_in[0];
    // d_in[1] router_out  (unused by reference)
    // d_in[2] topk_neuron_idx (unused by reference)
    const float* tw    = (const float*)d_in[3];
    const float* sn    = (const float*)d_in[4];
    const float* ctx   = (const float*)d_in[5];
    const float* Wq    = (const float*)d_in[6];
    const float* bq    = (const float*)d_in[7];
    const float* Wk    = (const float*)d_in[8];
    const float* bk    = (const float*)d_in[9];
    const float* Wv    = (const float*)d_in[10];
    const float* bv    = (const float*)d_in[11];
    const float* pq    = (const float*)d_in[12];
    const float* Wup   = (const float*)d_in[13];
    const float* bup   = (const float*)d_in[14];
    const float* Wdown = (const float*)d_in[15];
    const float* bdown = (const float*)d_in[16];
    float* out = (float*)d_out;

    float *Qp, *Kp, *Vp, *comb, *h;
    cudaGetSymbolAddress((void**)&Qp,   g_Q);
    cudaGetSymbolAddress((void**)&Kp,   g_K);
    cudaGetSymbolAddress((void**)&Vp,   g_V);
    cudaGetSymbolAddress((void**)&comb, g_comb);
    cudaGetSymbolAddress((void**)&h,    g_h);

    dim3 blk(256);

    // QKV: [32768,1024] @ [1024,1024]^T
    dim3 gq(Dd / GBN, MQKV / GBM);          // (16, 256)
    gemm_tf32<<<gq, blk>>>(sn, Wq, bq, Qp, MQKV, Dd, Dd, 0);
    gemm_tf32<<<gq, blk>>>(sn, Wk, bk, Kp, MQKV, Dd, Dd, 0);
    gemm_tf32<<<gq, blk>>>(sn, Wv, bv, Vp, MQKV, Dd, Dd, 0);

    // Fused attention / pattern selection / aggregation -> combined
    attn_fused<<<NTOK, blk>>>(Qp, Kp, Vp, pq, x, ctx, tw, comb);

    // FFN up (+exact GELU): [4096,1024] @ [4096,1024]^T -> [4096,4096]
    dim3 gu(DFFd / GBN, NTOK / GBM);        // (64, 32)
    gemm_tf32<<<gu, blk>>>(comb, Wup, bup, h, NTOK, DFFd, Dd, 1);

    // FFN down: [4096,4096] @ [1024,4096]^T -> [4096,1024]
    dim3 gd(Dd / GBN, NTOK / GBM);          // (16, 32)
    gemm_tf32<<<gd, blk>>>(h, Wdown, bdown, out, NTOK, Dd, DFFd, 0);
}

// round 3
// speedup vs baseline: 1.7638x; 1.7638x over previous
#include <cuda_runtime.h>
#include <math.h>
#include <stdint.h>

// Problem constants
#define Bb    2
#define Ss    2048
#define Kn    8
#define Dd    1024
#define DFFd  4096
#define NTOK  (Bb*Ss)        // 4096 tokens
#define MQKV  (NTOK*Kn)      // 32768 rows for QKV GEMM

// ----------------------------------------------------------------------------
// Scratch (static device globals; no runtime allocation)
// ----------------------------------------------------------------------------
__device__ float g_Q[(size_t)MQKV * Dd];
__device__ float g_K[(size_t)MQKV * Dd];
__device__ float g_V[(size_t)MQKV * Dd];
__device__ float g_comb[(size_t)NTOK * Dd];
__device__ float g_h[(size_t)NTOK * DFFd];
__device__ float g_Wqkv[(size_t)3 * Dd * Dd];   // packed+rounded Wq|Wk|Wv
__device__ float g_bqkv[3 * Dd];                // packed bq|bk|bv
__device__ float g_Wup[(size_t)DFFd * Dd];      // rounded
__device__ float g_Wdn[(size_t)Dd * DFFd];      // rounded

// ----------------------------------------------------------------------------
// Helpers (baseline ISA only: cp.async / ldmatrix / mma.sync)
// ----------------------------------------------------------------------------
__device__ __forceinline__ float to_tf32(float x) {
    float r; asm("cvt.rna.tf32.f32 %0, %1;" : "=f"(r) : "f"(x)); return r;
}
__device__ __forceinline__ uint32_t rnd_u32(uint32_t x) {
    float f = __uint_as_float(x);
    return __float_as_uint(to_tf32(f));
}
__device__ __forceinline__ uint32_t smem_u32(const void* p) {
    uint32_t a;
    asm("{ .reg .u64 t; cvta.to.shared.u64 t, %1; cvt.u32.u64 %0, t; }" : "=r"(a) : "l"(p));
    return a;
}
#define SW128(o) ((o) ^ (((o) >> 3) & 0x70))

__device__ __forceinline__ void cpa16(uint32_t s, const void* g) {
    asm volatile("cp.async.cg.shared.global [%0], [%1], 16;" :: "r"(s), "l"(g));
}
__device__ __forceinline__ void cpa_commit() {
    asm volatile("cp.async.commit_group;" ::: "memory");
}
template <int N>
__device__ __forceinline__ void cpa_wait() {
    asm volatile("cp.async.wait_group %0;" :: "n"(N) : "memory");
}
__device__ __forceinline__ void ldsm4(uint32_t& r0, uint32_t& r1, uint32_t& r2, uint32_t& r3,
                                      uint32_t addr) {
    asm volatile("ldmatrix.sync.aligned.m8n8.x4.shared.b16 {%0,%1,%2,%3}, [%4];"
                 : "=r"(r0), "=r"(r1), "=r"(r2), "=r"(r3) : "r"(addr));
}
__device__ __forceinline__ void mma_tf32(float* c, uint32_t a0, uint32_t a1, uint32_t a2,
                                         uint32_t a3, uint32_t b0, uint32_t b1) {
    asm volatile(
        "mma.sync.aligned.m16n8k8.row.col.f32.tf32.tf32.f32 "
        "{%0,%1,%2,%3}, {%4,%5,%6,%7}, {%8,%9}, {%0,%1,%2,%3};"
        : "+f"(c[0]), "+f"(c[1]), "+f"(c[2]), "+f"(c[3])
        : "r"(a0), "r"(a1), "r"(a2), "r"(a3), "r"(b0), "r"(b1));
}
__device__ __forceinline__ float gelu_exact(float v) {
    return 0.5f * v * (1.0f + erff(v * 0.70710678118654752440f));
}

// ----------------------------------------------------------------------------
// tf32 mma.sync GEMM:  C[M,N] = A[M,K] @ B[N,K]^T + bias (+GELU)
// CTA 128x128, BK=32, 3-stage cp.async, SW128 swizzle, ldmatrix fragments.
// 8 warps: wm = warp&3 (32 rows each), wn = warp>>2 (64 cols each).
// B (weights) pre-rounded to tf32; A rounded on fragments iff round_a.
// ----------------------------------------------------------------------------
#define STAGE_BYTES 32768
#define B_OFF       16384
#define DYN_SMEM    (3 * STAGE_BYTES)

__global__ __launch_bounds__(256, 2) void gemm_mma(
    const float* __restrict__ A, int lda,
    const float* __restrict__ Bw,
    const float* __restrict__ bias,
    float* __restrict__ C0, float* __restrict__ C1, float* __restrict__ C2,
    int ldc, int Kd, int Nt, int band_m, int act, int qkv, int round_a)
{
    extern __shared__ __align__(128) char dsm[];
    const uint32_t sbase = smem_u32(dsm);

    const int t    = threadIdx.x;
    const int warp = t >> 5;
    const int lane = t & 31;

    // band rasterization: m-tiles fast within a band -> B panel stays in L2
    const int tpb  = band_m * Nt;
    const int band = blockIdx.x / tpb;
    const int rem  = blockIdx.x % tpb;
    const int m0   = (band * band_m + rem % band_m) * 128;
    const int n0   = (rem / band_m) * 128;

    float* Cdst; int coff;
    if (qkv) {
        int sel = n0 >> 10;
        Cdst = (sel == 0) ? C0 : ((sel == 1) ? C1 : C2);
        coff = n0 & 1023;
    } else { Cdst = C0; coff = n0; }

    const int wm0 = (warp & 3) * 32;
    const int wn0 = (warp >> 2) * 64;

    float acc[64];
    #pragma unroll
    for (int i = 0; i < 64; i++) acc[i] = 0.0f;

    const int NIT = Kd >> 5;

    auto load_stage = [&](int sl, int kIt) {
        const int k0 = kIt << 5;
        const uint32_t sb = sbase + sl * STAGE_BYTES;
        #pragma unroll
        for (int i = 0; i < 4; i++) {
            int gi = t + 256 * i;
            int row = gi >> 3, g = gi & 7;
            cpa16(sb + SW128((uint32_t)(row * 128 + g * 16)),
                  A + (size_t)(m0 + row) * lda + k0 + g * 4);
        }
        #pragma unroll
        for (int i = 0; i < 4; i++) {
            int gi = t + 256 * i;
            int row = gi >> 3, g = gi & 7;
            cpa16(sb + B_OFF + SW128((uint32_t)(row * 128 + g * 16)),
                  Bw + (size_t)(n0 + row) * Kd + k0 + g * 4);
        }
        cpa_commit();
    };

    load_stage(0, 0);
    load_stage(1, 1);

    const int sub = lane >> 3, rr = lane & 7;

    for (int it = 0; it < NIT; it++) {
        if (it + 2 < NIT) load_stage((it + 2) % 3, it + 2);
        if (it + 2 < NIT)      cpa_wait<2>();
        else if (it + 1 < NIT) cpa_wait<1>();
        else                   cpa_wait<0>();
        __syncthreads();

        const uint32_t ab = sbase + (it % 3) * STAGE_BYTES;
        const uint32_t bb = ab + B_OFF;

        #pragma unroll
        for (int kk = 0; kk < 32; kk += 8) {
            // A fragments: 2 ldmatrix.x4 (m16 each)
            uint32_t a[8];
            #pragma unroll
            for (int mf = 0; mf < 2; mf++) {
                int row = wm0 + mf * 16 + ((sub & 1) << 3) + rr;
                uint32_t off = (uint32_t)(row * 128 + kk * 4 + ((sub >> 1) << 4));
                ldsm4(a[mf * 4 + 0], a[mf * 4 + 1], a[mf * 4 + 2], a[mf * 4 + 3],
                      ab + SW128(off));
            }
            if (round_a) {
                #pragma unroll
                for (int i = 0; i < 8; i++) a[i] = rnd_u32(a[i]);
            }
            // B fragments: 4 ldmatrix.x4, each covers 2 n-chunks of 8
            #pragma unroll
            for (int cp = 0; cp < 4; cp++) {
                uint32_t b0, b1, b2, b3;
                int nrow = wn0 + cp * 16 + ((sub >> 1) << 3) + rr;
                uint32_t off = (uint32_t)(nrow * 128 + kk * 4 + ((sub & 1) << 4));
                ldsm4(b0, b1, b2, b3, bb + SW128(off));
                #pragma unroll
                for (int mf = 0; mf < 2; mf++) {
                    mma_tf32(&acc[(mf * 8 + cp * 2 + 0) * 4], a[mf * 4 + 0], a[mf * 4 + 1],
                             a[mf * 4 + 2], a[mf * 4 + 3], b0, b1);
                    mma_tf32(&acc[(mf * 8 + cp * 2 + 1) * 4], a[mf * 4 + 0], a[mf * 4 + 1],
                             a[mf * 4 + 2], a[mf * 4 + 3], b2, b3);
                }
            }
        }
        __syncthreads();
    }

    // Epilogue: direct float2 stores (32B sectors fully used), bias + optional GELU
    const int gid = lane >> 2, ctg = lane & 3;
    #pragma unroll
    for (int mf = 0; mf < 2; mf++) {
        #pragma unroll
        for (int nf = 0; nf < 8; nf++) {
            float* c = &acc[(mf * 8 + nf) * 4];
            int nbias = n0 + wn0 + nf * 8 + ctg * 2;
            float2 bv = *(const float2*)(bias + nbias);
            float v0 = c[0] + bv.x, v1 = c[1] + bv.y;
            float v2 = c[2] + bv.x, v3 = c[3] + bv.y;
            if (act == 1) {
                v0 = to_tf32(gelu_exact(v0)); v1 = to_tf32(gelu_exact(v1));
                v2 = to_tf32(gelu_exact(v2)); v3 = to_tf32(gelu_exact(v3));
            }
            int r0 = m0 + wm0 + mf * 16 + gid;
            int cc = coff + wn0 + nf * 8 + ctg * 2;
            float2 o0 = {v0, v1}, o1 = {v2, v3};
            *(float2*)(Cdst + (size_t)r0 * ldc + cc) = o0;
            *(float2*)(Cdst + (size_t)(r0 + 8) * ldc + cc) = o1;
        }
    }
}

// ----------------------------------------------------------------------------
// Prepass: tf32 rounding / packing (weights only; A rounded in-kernel)
// ----------------------------------------------------------------------------
__global__ void round_k(float* __restrict__ d, const float* __restrict__ s, int n4) {
    int i = blockIdx.x * blockDim.x + threadIdx.x;
    if (i < n4) {
        float4 v = ((const float4*)s)[i];
        v.x = to_tf32(v.x); v.y = to_tf32(v.y); v.z = to_tf32(v.z); v.w = to_tf32(v.w);
        ((float4*)d)[i] = v;
    }
}
__global__ void pack3_k(float* __restrict__ d, const float* __restrict__ a,
                        const float* __restrict__ b, const float* __restrict__ c,
                        int seg4, int rnd) {
    int i = blockIdx.x * blockDim.x + threadIdx.x;
    if (i < 3 * seg4) {
        const float* s = (i < seg4) ? a : ((i < 2 * seg4) ? b : c);
        int j = i - ((i < seg4) ? 0 : ((i < 2 * seg4) ? seg4 : 2 * seg4));
        float4 v = ((const float4*)s)[j];
        if (rnd) { v.x = to_tf32(v.x); v.y = to_tf32(v.y); v.z = to_tf32(v.z); v.w = to_tf32(v.w); }
        ((float4*)d)[i] = v;
    }
}

// ----------------------------------------------------------------------------
// Fused per-token attention / pattern-selection / aggregation kernel.
// Stage 1 chunked (q buffer 8 regs) + launch_bounds(256,3) for occupancy.
// ----------------------------------------------------------------------------
__global__ __launch_bounds__(256, 3) void attn_fused(
    const float* __restrict__ Q, const float* __restrict__ Km, const float* __restrict__ V,
    const float* __restrict__ pq, const float* __restrict__ x, const float* __restrict__ ctx,
    const float* __restrict__ tw, float* __restrict__ comb)
{
    const int tok  = blockIdx.x;
    const int t    = threadIdx.x;
    const int warp = t >> 5;
    const int lane = t & 31;
    const float scale = 0.03125f;

    __shared__ float sI[8][1028];
    __shared__ float sWI[1028];
    __shared__ float sCtx[1024];
    __shared__ float sA[8][8];
    __shared__ float sW[8];
    __shared__ float sNB[32], sCB[32];
    __shared__ float sSel[4][8];
    __shared__ float sTw[4];
    __shared__ int   sTi[4];
    __shared__ float sFA[8];

    const size_t base = (size_t)tok * 8 * 1024;
    const float* Qt = Q + base;
    const float* Kt = Km + base;
    const float* Vt = V + base;

    if (t < 8) sW[t] = tw[tok * 8 + t];
    #pragma unroll
    for (int r = 0; r < 4; r++) sCtx[t + 256 * r] = ctx[(size_t)tok * 1024 + t + 256 * r];

    // ---- Stage 1: scores + softmax (warp i -> row i), chunked over D ----
    {
        const int i = warp;
        float sc[8] = {0, 0, 0, 0, 0, 0, 0, 0};
        for (int c = 0; c < 4; c++) {
            float qc[8];
            #pragma unroll
            for (int u = 0; u < 8; u++) qc[u] = Qt[i * 1024 + c * 256 + u * 32 + lane];
            #pragma unroll
            for (int j = 0; j < 8; j++) {
                float a = 0.0f;
                #pragma unroll
                for (int u = 0; u < 8; u++)
                    a = fmaf(qc[u], Kt[j * 1024 + c * 256 + u * 32 + lane], a);
                sc[j] += a;
            }
        }
        #pragma unroll
        for (int j = 0; j < 8; j++) {
            float a = sc[j];
            #pragma unroll
            for (int o = 16; o > 0; o >>= 1) a += __shfl_xor_sync(0xffffffffu, a, o);
            sc[j] = a * scale;
        }
        if (lane == 0) {
            float m = sc[0];
            #pragma unroll
            for (int j = 1; j < 8; j++) m = fmaxf(m, sc[j]);
            float e[8], s = 0.0f;
            #pragma unroll
            for (int j = 0; j < 8; j++) { e[j] = expf(sc[j] - m); s += e[j]; }
            float inv = 1.0f / s;
            #pragma unroll
            for (int j = 0; j < 8; j++) sA[i][j] = e[j] * inv;
        }
    }
    __syncthreads();

    // ---- Stage 2: interacted = attn @ V, plus weighted sum ----
    #pragma unroll
    for (int r = 0; r < 4; r++) {
        int d = t + 256 * r;
        float a[8] = {0,0,0,0,0,0,0,0};
        #pragma unroll
        for (int j = 0; j < 8; j++) {
            float v = Vt[j * 1024 + d];
            #pragma unroll
            for (int i = 0; i < 8; i++) a[i] = fmaf(sA[i][j], v, a[i]);
        }
        float wi = 0.0f;
        #pragma unroll
        for (int i = 0; i < 8; i++) { sI[i][d] = a[i]; wi = fmaf(sW[i], a[i], wi); }
        sWI[d] = wi;
    }
    __syncthreads();

    // ---- Stage 3: neuron_based + context_based ----
    #pragma unroll
    for (int q = 0; q < 4; q++) {
        int p = warp * 4 + q;
        const float* pr = pq + (size_t)p * 1024;
        float nb = 0.0f, cb = 0.0f;
        #pragma unroll
        for (int u = 0; u < 32; u++) {
            int d = u * 32 + lane;
            float pv = pr[d];
            nb = fmaf(pv, sWI[d], nb);
            cb = fmaf(pv, sCtx[d], cb);
        }
        #pragma unroll
        for (int o = 16; o > 0; o >>= 1) {
            nb += __shfl_xor_sync(0xffffffffu, nb, o);
            cb += __shfl_xor_sync(0xffffffffu, cb, o);
        }
        if (lane == 0) { sNB[p] = nb * scale; sCB[p] = cb; }
    }
    __syncthreads();

    // ---- Stage 4: top-4 + softmax of the 4 (warp 0) ----
    if (warp == 0) {
        float s = 0.5f * sNB[lane] + 0.5f * sCB[lane];
        float vals[4]; int ids[4];
        #pragma unroll
        for (int r = 0; r < 4; r++) {
            float v = s; int idx = lane;
            #pragma unroll
            for (int o = 16; o > 0; o >>= 1) {
                float ov = __shfl_xor_sync(0xffffffffu, v, o);
                int   oi = __shfl_xor_sync(0xffffffffu, idx, o);
                if (ov > v || (ov == v && oi < idx)) { v = ov; idx = oi; }
            }
            vals[r] = v; ids[r] = idx;
            if (lane == idx) s = -3.4e38f;
        }
        if (lane == 0) {
            float m = fmaxf(fmaxf(vals[0], vals[1]), fmaxf(vals[2], vals[3]));
            float e0 = expf(vals[0] - m), e1 = expf(vals[1] - m);
            float e2 = expf(vals[2] - m), e3 = expf(vals[3] - m);
            float inv = 1.0f / (e0 + e1 + e2 + e3);
            sTw[0] = e0 * inv; sTw[1] = e1 * inv; sTw[2] = e2 * inv; sTw[3] = e3 * inv;
            sTi[0] = ids[0]; sTi[1] = ids[1]; sTi[2] = ids[2]; sTi[3] = ids[3];
        }
    }
    __syncthreads();

    // ---- Stage 5: selected nps rows, softmax, weight ----
    if (warp < 4) {
        int pi = sTi[warp];
        const float* pr = pq + (size_t)pi * 1024;
        float sel[8] = {0,0,0,0,0,0,0,0};
        for (int c = 0; c < 4; c++) {
            float pv[8];
            #pragma unroll
            for (int u = 0; u < 8; u++) pv[u] = pr[c * 256 + u * 32 + lane];
            #pragma unroll
            for (int k = 0; k < 8; k++) {
                float a = 0.0f;
                #pragma unroll
                for (int u = 0; u < 8; u++)
                    a = fmaf(pv[u], sI[k][c * 256 + u * 32 + lane], a);
                sel[k] += a;
            }
        }
        #pragma unroll
        for (int k = 0; k < 8; k++) {
            float a = sel[k];
            #pragma unroll
            for (int o = 16; o > 0; o >>= 1) a += __shfl_xor_sync(0xffffffffu, a, o);
            sel[k] = a * scale;
        }
        if (lane == 0) {
            float m = sel[0];
            #pragma unroll
            for (int k = 1; k < 8; k++) m = fmaxf(m, sel[k]);
            float e[8], sum = 0.0f;
            #pragma unroll
            for (int k = 0; k < 8; k++) { e[k] = expf(sel[k] - m); sum += e[k]; }
            float f = sTw[warp] / sum;
            #pragma unroll
            for (int k = 0; k < 8; k++) sSel[warp][k] = e[k] * f;
        }
    }
    __syncthreads();
    if (t < 8) sFA[t] = sSel[0][t] + sSel[1][t] + sSel[2][t] + sSel[3][t];
    __syncthreads();

    // ---- Stage 6: aggregated + residual -> combined (tf32-rounded) ----
    float fa[8];
    #pragma unroll
    for (int k = 0; k < 8; k++) fa[k] = sFA[k];
    #pragma unroll
    for (int r = 0; r < 4; r++) {
        int d = t + 256 * r;
        float a = x[(size_t)tok * 1024 + d];
        #pragma unroll
        for (int k = 0; k < 8; k++) a = fmaf(fa[k], sI[k][d], a);
        comb[(size_t)tok * 1024 + d] = to_tf32(a);
    }
}

// ----------------------------------------------------------------------------
// Launch
// ----------------------------------------------------------------------------
extern "C" void kernel_launch(void* const* d_in, const int* in_sizes, int n_in,
                              void* d_out, int out_size)
{
    const float* x     = (const float*)d_in[0];
    const float* tw    = (const float*)d_in[3];
    const float* sn    = (const float*)d_in[4];
    const float* ctx   = (const float*)d_in[5];
    const float* Wq    = (const float*)d_in[6];
    const float* bq    = (const float*)d_in[7];
    const float* Wk    = (const float*)d_in[8];
    const float* bk    = (const float*)d_in[9];
    const float* Wv    = (const float*)d_in[10];
    const float* bv    = (const float*)d_in[11];
    const float* pq    = (const float*)d_in[12];
    const float* Wup   = (const float*)d_in[13];
    const float* bup   = (const float*)d_in[14];
    const float* Wdown = (const float*)d_in[15];
    const float* bdown = (const float*)d_in[16];
    float* out = (float*)d_out;

    float *Qp, *Kp, *Vp, *comb, *h, *Wqkv, *bqkv, *Wupr, *Wdnr;
    cudaGetSymbolAddress((void**)&Qp,   g_Q);
    cudaGetSymbolAddress((void**)&Kp,   g_K);
    cudaGetSymbolAddress((void**)&Vp,   g_V);
    cudaGetSymbolAddress((void**)&comb, g_comb);
    cudaGetSymbolAddress((void**)&h,    g_h);
    cudaGetSymbolAddress((void**)&Wqkv, g_Wqkv);
    cudaGetSymbolAddress((void**)&bqkv, g_bqkv);
    cudaGetSymbolAddress((void**)&Wupr, g_Wup);
    cudaGetSymbolAddress((void**)&Wdnr, g_Wdn);

    cudaFuncSetAttribute(gemm_mma, cudaFuncAttributeMaxDynamicSharedMemorySize, DYN_SMEM);

    // prepass: round+pack weights (A operands handled in-kernel / at producers)
    {
        int s4 = (Dd * Dd) / 4;
        pack3_k<<<(3 * s4 + 255) / 256, 256>>>(Wqkv, Wq, Wk, Wv, s4, 1);
        pack3_k<<<(3 * (Dd / 4) + 255) / 256, 256>>>(bqkv, bq, bk, bv, Dd / 4, 0);
        int u4 = (DFFd * Dd) / 4;
        round_k<<<(u4 + 255) / 256, 256>>>(Wupr, Wup, u4);
        round_k<<<(u4 + 255) / 256, 256>>>(Wdnr, Wdown, u4);
    }

    // QKV fused: [32768,1024] @ [3072,1024]^T  (Mt=256, Nt=24, band 8)
    gemm_mma<<<256 * 24, 256, DYN_SMEM>>>(sn, Dd, Wqkv, bqkv, Qp, Kp, Vp,
                                          Dd, Dd, 24, 8, 0, 1, 1);

    // fused attention -> comb (tf32-rounded)
    attn_fused<<<NTOK, 256>>>(Qp, Kp, Vp, pq, x, ctx, tw, comb);

    // FFN up (+GELU, rounded): [4096,1024] @ [4096,1024]^T  (Mt=32, Nt=32, band 8)
    gemm_mma<<<32 * 32, 256, DYN_SMEM>>>(comb, Dd, Wupr, bup, h, h, h,
                                         DFFd, Dd, 32, 8, 1, 0, 0);

    // FFN down: [4096,4096] @ [1024,4096]^T  (Mt=32, Nt=8, band 16)
    gemm_mma<<<32 * 8, 256, DYN_SMEM>>>(h, DFFd, Wdnr, bdown, out, out, out,
                                        Dd, DFFd, 8, 16, 0, 0, 0);
}

// round 4
// speedup vs baseline: 3.7973x; 2.1529x over previous
#include <cuda_runtime.h>
#include <math.h>
#include <stdint.h>

// Problem constants
#define Bb    2
#define Ss    2048
#define Kn    8
#define Dd    1024
#define DFFd  4096
#define NTOK  (Bb*Ss)        // 4096 tokens
#define MQKV  (NTOK*Kn)      // 32768 rows

// ----------------------------------------------------------------------------
// Scratch (static device globals; zero-initialized at load, no runtime alloc)
// ----------------------------------------------------------------------------
__device__ float g_U[(size_t)MQKV * Dd];        // sn @ Mt^T
__device__ float g_comb[(size_t)NTOK * Dd];
__device__ float g_h[(size_t)NTOK * DFFd];
__device__ float g_aggmix[(size_t)NTOK * Dd];
__device__ float g_sfa[NTOK];
__device__ float g_Wqt[(size_t)Dd * Dd];        // Wq^T (rounded)
__device__ float g_Wkt[(size_t)Dd * Dd];        // Wk^T (rounded)
__device__ float g_Mt[(size_t)Dd * Dd];         // Wkt @ Wqt^T (rounded)
__device__ float g_Wvr[(size_t)Dd * Dd];        // rounded Wv
__device__ float g_Wupr[(size_t)DFFd * Dd];
__device__ float g_Wdnr[(size_t)Dd * DFFd];
__device__ float g_PV[32 * Dd];                 // pq @ Wv
__device__ float g_vqk[Dd];                     // Wq^T bk
__device__ float g_vkq[Dd];                     // Wk^T bq
__device__ float g_pqbv[32];                    // pq_p . bv
__device__ float g_c0[1];                       // bq . bk
__device__ float g_zeros[Dd];                   // zero bias

// ----------------------------------------------------------------------------
// Helpers (baseline ISA only: cp.async / ldmatrix / mma.sync)
// ----------------------------------------------------------------------------
__device__ __forceinline__ float to_tf32(float x) {
    float r; asm("cvt.rna.tf32.f32 %0, %1;" : "=f"(r) : "f"(x)); return r;
}
__device__ __forceinline__ uint32_t rnd_u32(uint32_t x) {
    return __float_as_uint(to_tf32(__uint_as_float(x)));
}
__device__ __forceinline__ uint32_t smem_u32(const void* p) {
    uint32_t a;
    asm("{ .reg .u64 t; cvta.to.shared.u64 t, %1; cvt.u32.u64 %0, t; }" : "=r"(a) : "l"(p));
    return a;
}
#define SW128(o) ((o) ^ (((o) >> 3) & 0x70))

__device__ __forceinline__ void cpa16(uint32_t s, const void* g) {
    asm volatile("cp.async.cg.shared.global [%0], [%1], 16;" :: "r"(s), "l"(g));
}
__device__ __forceinline__ void cpa_commit() {
    asm volatile("cp.async.commit_group;" ::: "memory");
}
template <int N>
__device__ __forceinline__ void cpa_wait() {
    asm volatile("cp.async.wait_group %0;" :: "n"(N) : "memory");
}
__device__ __forceinline__ void ldsm4(uint32_t& r0, uint32_t& r1, uint32_t& r2, uint32_t& r3,
                                      uint32_t addr) {
    asm volatile("ldmatrix.sync.aligned.m8n8.x4.shared.b16 {%0,%1,%2,%3}, [%4];"
                 : "=r"(r0), "=r"(r1), "=r"(r2), "=r"(r3) : "r"(addr));
}
__device__ __forceinline__ void mma_tf32(float* c, uint32_t a0, uint32_t a1, uint32_t a2,
                                         uint32_t a3, uint32_t b0, uint32_t b1) {
    asm volatile(
        "mma.sync.aligned.m16n8k8.row.col.f32.tf32.tf32.f32 "
        "{%0,%1,%2,%3}, {%4,%5,%6,%7}, {%8,%9}, {%0,%1,%2,%3};"
        : "+f"(c[0]), "+f"(c[1]), "+f"(c[2]), "+f"(c[3])
        : "r"(a0), "r"(a1), "r"(a2), "r"(a3), "r"(b0), "r"(b1));
}
__device__ __forceinline__ float gelu_exact(float v) {
    return 0.5f * v * (1.0f + erff(v * 0.70710678118654752440f));
}

// ----------------------------------------------------------------------------
// tf32 mma.sync GEMM:  C[M,N] = A[M,K] @ B[N,K]^T + epilogue
// act: 0 = +bias; 1 = +bias,gelu,round; 2 = +bias,round;
//      3 = +xadd +sfa[row]*bias, round  (aggregation epilogue)
// ----------------------------------------------------------------------------
#define STAGE_BYTES 32768
#define B_OFF       16384
#define DYN_SMEM    (3 * STAGE_BYTES)

__global__ __launch_bounds__(256, 2) void gemm_mma(
    const float* __restrict__ A, int lda,
    const float* __restrict__ Bw,
    const float* __restrict__ bias,
    float* __restrict__ C, int ldc,
    int Kd, int Nt, int band_m, int act, int round_a,
    const float* __restrict__ xadd, const float* __restrict__ sfa)
{
    extern __shared__ __align__(128) char dsm[];
    const uint32_t sbase = smem_u32(dsm);

    const int t    = threadIdx.x;
    const int warp = t >> 5;
    const int lane = t & 31;

    const int tpb  = band_m * Nt;
    const int band = blockIdx.x / tpb;
    const int rem  = blockIdx.x % tpb;
    const int m0   = (band * band_m + rem % band_m) * 128;
    const int n0   = (rem / band_m) * 128;

    const int wm0 = (warp & 3) * 32;
    const int wn0 = (warp >> 2) * 64;

    float acc[64];
    #pragma unroll
    for (int i = 0; i < 64; i++) acc[i] = 0.0f;

    const int NIT = Kd >> 5;

    auto load_stage = [&](int sl, int kIt) {
        const int k0 = kIt << 5;
        const uint32_t sb = sbase + sl * STAGE_BYTES;
        #pragma unroll
        for (int i = 0; i < 4; i++) {
            int gi = t + 256 * i;
            int row = gi >> 3, g = gi & 7;
            cpa16(sb + SW128((uint32_t)(row * 128 + g * 16)),
                  A + (size_t)(m0 + row) * lda + k0 + g * 4);
        }
        #pragma unroll
        for (int i = 0; i < 4; i++) {
            int gi = t + 256 * i;
            int row = gi >> 3, g = gi & 7;
            cpa16(sb + B_OFF + SW128((uint32_t)(row * 128 + g * 16)),
                  Bw + (size_t)(n0 + row) * Kd + k0 + g * 4);
        }
        cpa_commit();
    };

    load_stage(0, 0);
    load_stage(1, 1);

    const int sub = lane >> 3, rr = lane & 7;

    for (int it = 0; it < NIT; it++) {
        if (it + 2 < NIT) load_stage((it + 2) % 3, it + 2);
        if (it + 2 < NIT)      cpa_wait<2>();
        else if (it + 1 < NIT) cpa_wait<1>();
        else                   cpa_wait<0>();
        __syncthreads();

        const uint32_t ab = sbase + (it % 3) * STAGE_BYTES;
        const uint32_t bb = ab + B_OFF;

        #pragma unroll
        for (int kk = 0; kk < 32; kk += 8) {
            uint32_t a[8];
            #pragma unroll
            for (int mf = 0; mf < 2; mf++) {
                int row = wm0 + mf * 16 + ((sub & 1) << 3) + rr;
                uint32_t off = (uint32_t)(row * 128 + kk * 4 + ((sub >> 1) << 4));
                ldsm4(a[mf * 4 + 0], a[mf * 4 + 1], a[mf * 4 + 2], a[mf * 4 + 3],
                      ab + SW128(off));
            }
            if (round_a) {
                #pragma unroll
                for (int i = 0; i < 8; i++) a[i] = rnd_u32(a[i]);
            }
            #pragma unroll
            for (int cp = 0; cp < 4; cp++) {
                uint32_t b0, b1, b2, b3;
                int nrow = wn0 + cp * 16 + ((sub >> 1) << 3) + rr;
                uint32_t off = (uint32_t)(nrow * 128 + kk * 4 + ((sub & 1) << 4));
                ldsm4(b0, b1, b2, b3, bb + SW128(off));
                #pragma unroll
                for (int mf = 0; mf < 2; mf++) {
                    mma_tf32(&acc[(mf * 8 + cp * 2 + 0) * 4], a[mf * 4 + 0], a[mf * 4 + 1],
                             a[mf * 4 + 2], a[mf * 4 + 3], b0, b1);
                    mma_tf32(&acc[(mf * 8 + cp * 2 + 1) * 4], a[mf * 4 + 0], a[mf * 4 + 1],
                             a[mf * 4 + 2], a[mf * 4 + 3], b2, b3);
                }
            }
        }
        __syncthreads();
    }

    const int gid = lane >> 2, ctg = lane & 3;
    #pragma unroll
    for (int mf = 0; mf < 2; mf++) {
        int r0 = m0 + wm0 + mf * 16 + gid;
        float s0 = 0.0f, s1 = 0.0f;
        if (act == 3) { s0 = sfa[r0]; s1 = sfa[r0 + 8]; }
        #pragma unroll
        for (int nf = 0; nf < 8; nf++) {
            float* c = &acc[(mf * 8 + nf) * 4];
            int cc = n0 + wn0 + nf * 8 + ctg * 2;
            float2 bv2 = *(const float2*)(bias + cc);
            float v0 = c[0], v1 = c[1], v2 = c[2], v3 = c[3];
            if (act == 3) {
                float2 x0 = *(const float2*)(xadd + (size_t)r0 * ldc + cc);
                float2 x1 = *(const float2*)(xadd + (size_t)(r0 + 8) * ldc + cc);
                v0 = to_tf32(v0 + x0.x + s0 * bv2.x);
                v1 = to_tf32(v1 + x0.y + s0 * bv2.y);
                v2 = to_tf32(v2 + x1.x + s1 * bv2.x);
                v3 = to_tf32(v3 + x1.y + s1 * bv2.y);
            } else {
                v0 += bv2.x; v1 += bv2.y; v2 += bv2.x; v3 += bv2.y;
                if (act == 1) {
                    v0 = to_tf32(gelu_exact(v0)); v1 = to_tf32(gelu_exact(v1));
                    v2 = to_tf32(gelu_exact(v2)); v3 = to_tf32(gelu_exact(v3));
                } else if (act == 2) {
                    v0 = to_tf32(v0); v1 = to_tf32(v1);
                    v2 = to_tf32(v2); v3 = to_tf32(v3);
                }
            }
            float2 o0 = {v0, v1}, o1 = {v2, v3};
            *(float2*)(C + (size_t)r0 * ldc + cc) = o0;
            *(float2*)(C + (size_t)(r0 + 8) * ldc + cc) = o1;
        }
    }
}

// ----------------------------------------------------------------------------
// Prepass kernels
// ----------------------------------------------------------------------------
__global__ void round_k(float* __restrict__ d, const float* __restrict__ s, int n4) {
    int i = blockIdx.x * blockDim.x + threadIdx.x;
    if (i < n4) {
        float4 v = ((const float4*)s)[i];
        v.x = to_tf32(v.x); v.y = to_tf32(v.y); v.z = to_tf32(v.z); v.w = to_tf32(v.w);
        ((float4*)d)[i] = v;
    }
}
__global__ void transpose_rnd(float* __restrict__ dst, const float* __restrict__ src) {
    __shared__ float tile[32][33];
    int bx = blockIdx.x * 32, by = blockIdx.y * 32;
    int tx = threadIdx.x, ty = threadIdx.y;
    #pragma unroll
    for (int r = 0; r < 32; r += 8)
        tile[ty + r][tx] = src[(size_t)(by + ty + r) * Dd + bx + tx];
    __syncthreads();
    #pragma unroll
    for (int r = 0; r < 32; r += 8)
        dst[(size_t)(bx + ty + r) * Dd + by + tx] = to_tf32(tile[tx][ty + r]);
}
__global__ void prep_bias(float* __restrict__ vqk, float* __restrict__ vkq,
                          const float* __restrict__ Wq, const float* __restrict__ bk,
                          const float* __restrict__ Wk, const float* __restrict__ bq) {
    int idx = blockIdx.x * blockDim.x + threadIdx.x;
    if (idx < Dd) {
        float a = 0.0f;
        for (int e = 0; e < Dd; e++) a = fmaf(Wq[(size_t)e * Dd + idx], bk[e], a);
        vqk[idx] = a;
    } else if (idx < 2 * Dd) {
        int d = idx - Dd;
        float a = 0.0f;
        for (int e = 0; e < Dd; e++) a = fmaf(Wk[(size_t)e * Dd + d], bq[e], a);
        vkq[d] = a;
    }
}
__global__ void prep_small(float* __restrict__ pqbv, float* __restrict__ c0,
                           const float* __restrict__ pq, const float* __restrict__ bv,
                           const float* __restrict__ bq, const float* __restrict__ bk) {
    __shared__ float red[256];
    int b = blockIdx.x, t = threadIdx.x;
    float a = 0.0f;
    if (b < 32) {
        for (int e = t; e < Dd; e += 256) a = fmaf(pq[(size_t)b * Dd + e], bv[e], a);
    } else {
        for (int e = t; e < Dd; e += 256) a = fmaf(bq[e], bk[e], a);
    }
    red[t] = a; __syncthreads();
    for (int o = 128; o > 0; o >>= 1) { if (t < o) red[t] += red[t + o]; __syncthreads(); }
    if (t == 0) { if (b < 32) pqbv[b] = red[0]; else c0[0] = red[0]; }
}
__global__ void prep_pv(float* __restrict__ PV, const float* __restrict__ pq,
                        const float* __restrict__ Wv) {
    int d = blockIdx.x * 256 + threadIdx.x;
    int p = blockIdx.y;
    float a = 0.0f;
    for (int e = 0; e < Dd; e++) a = fmaf(pq[(size_t)p * Dd + e], Wv[(size_t)e * Dd + d], a);
    PV[(size_t)p * Dd + d] = a;
}

// ----------------------------------------------------------------------------
// Fused per-token attention (factored form). Reads U + sn; emits agg_mix + sfa.
// ----------------------------------------------------------------------------
#define ATTN_SMEM ((8 * 1028 * 2 + 1028 + 1024) * 4)

__global__ __launch_bounds__(256) void attn_fused(
    const float* __restrict__ U, const float* __restrict__ sn,
    const float* __restrict__ pq, const float* __restrict__ PV,
    const float* __restrict__ ctx, const float* __restrict__ tw,
    const float* __restrict__ vqk, const float* __restrict__ vkq,
    const float* __restrict__ pqbv, const float* __restrict__ c0p,
    float* __restrict__ aggmix, float* __restrict__ sfaout)
{
    extern __shared__ float dynsm[];
    float* sSn   = dynsm;                 // 8*1028
    float* sMix  = sSn + 8 * 1028;        // 8*1028
    float* sWMix = sMix + 8 * 1028;       // 1028
    float* sCtx  = sWMix + 1028;          // 1024

    __shared__ float sA[8][8];
    __shared__ float sW[8], sTq[8], sTk[8];
    __shared__ float sNB[32], sCB[32];
    __shared__ float sSel[4][8];
    __shared__ float sTw[4];
    __shared__ int   sTi[4];
    __shared__ float sFA[8];
    __shared__ float sC0;

    const int tok  = blockIdx.x;
    const int t    = threadIdx.x;
    const int warp = t >> 5;
    const int lane = t & 31;
    const float scale = 0.03125f;

    const float* snt = sn + (size_t)tok * 8 * 1024;
    const float* Ut  = U + (size_t)tok * 8 * 1024;

    if (t < 8) sW[t] = tw[tok * 8 + t];
    if (t == 0) sC0 = c0p[0];
    #pragma unroll
    for (int r = 0; r < 32; r++) {
        int idx = t + 256 * r;
        sSn[(idx >> 10) * 1028 + (idx & 1023)] = snt[idx];
    }
    #pragma unroll
    for (int r = 0; r < 4; r++) sCtx[t + 256 * r] = ctx[(size_t)tok * 1024 + t + 256 * r];
    __syncthreads();

    // ---- Stage 1: scores U_i . sn_j (+ bias corrections) ----
    float sc[8] = {0, 0, 0, 0, 0, 0, 0, 0};
    {
        const int i = warp;
        float tq = 0.0f, tk = 0.0f;
        for (int c = 0; c < 4; c++) {
            float uc[8];
            #pragma unroll
            for (int u = 0; u < 8; u++) uc[u] = Ut[i * 1024 + c * 256 + u * 32 + lane];
            #pragma unroll
            for (int j = 0; j < 8; j++) {
                float a = 0.0f;
                #pragma unroll
                for (int u = 0; u < 8; u++)
                    a = fmaf(uc[u], sSn[j * 1028 + c * 256 + u * 32 + lane], a);
                sc[j] += a;
            }
            #pragma unroll
            for (int u = 0; u < 8; u++) {
                int d = c * 256 + u * 32 + lane;
                float s = sSn[i * 1028 + d];
                tq = fmaf(s, vqk[d], tq);
                tk = fmaf(s, vkq[d], tk);
            }
        }
        #pragma unroll
        for (int j = 0; j < 8; j++) {
            float a = sc[j];
            #pragma unroll
            for (int o = 16; o > 0; o >>= 1) a += __shfl_xor_sync(0xffffffffu, a, o);
            sc[j] = a;
        }
        #pragma unroll
        for (int o = 16; o > 0; o >>= 1) {
            tq += __shfl_xor_sync(0xffffffffu, tq, o);
            tk += __shfl_xor_sync(0xffffffffu, tk, o);
        }
        if (lane == 0) { sTq[i] = tq; sTk[i] = tk; }
    }
    __syncthreads();
    {
        const int i = warp;
        float tqi = sTq[i], c0v = sC0;
        float f[8];
        #pragma unroll
        for (int j = 0; j < 8; j++) f[j] = (sc[j] + tqi + sTk[j] + c0v) * scale;
        if (lane == 0) {
            float m = f[0];
            #pragma unroll
            for (int j = 1; j < 8; j++) m = fmaxf(m, f[j]);
            float e[8], s = 0.0f;
            #pragma unroll
            for (int j = 0; j < 8; j++) { e[j] = expf(f[j] - m); s += e[j]; }
            float inv = 1.0f / s;
            #pragma unroll
            for (int j = 0; j < 8; j++) sA[i][j] = e[j] * inv;
        }
    }
    __syncthreads();

    // ---- Stage 2: mix = attn @ sn; wmix ----
    #pragma unroll
    for (int r = 0; r < 4; r++) {
        int d = t + 256 * r;
        float a[8] = {0,0,0,0,0,0,0,0};
        #pragma unroll
        for (int j = 0; j < 8; j++) {
            float s = sSn[j * 1028 + d];
            #pragma unroll
            for (int i = 0; i < 8; i++) a[i] = fmaf(sA[i][j], s, a[i]);
        }
        float wm = 0.0f;
        #pragma unroll
        for (int i = 0; i < 8; i++) { sMix[i * 1028 + d] = a[i]; wm = fmaf(sW[i], a[i], wm); }
        sWMix[d] = wm;
    }
    __syncthreads();

    // ---- Stage 3: neuron_based (PV) + context_based (pq) ----
    float swsum = sW[0] + sW[1] + sW[2] + sW[3] + sW[4] + sW[5] + sW[6] + sW[7];
    #pragma unroll
    for (int q = 0; q < 4; q++) {
        int p = warp * 4 + q;
        const float* PVp = PV + (size_t)p * 1024;
        const float* pqp = pq + (size_t)p * 1024;
        float nb = 0.0f, cb = 0.0f;
        #pragma unroll
        for (int u = 0; u < 32; u++) {
            int d = u * 32 + lane;
            nb = fmaf(PVp[d], sWMix[d], nb);
            cb = fmaf(pqp[d], sCtx[d], cb);
        }
        #pragma unroll
        for (int o = 16; o > 0; o >>= 1) {
            nb += __shfl_xor_sync(0xffffffffu, nb, o);
            cb += __shfl_xor_sync(0xffffffffu, cb, o);
        }
        if (lane == 0) { sNB[p] = (nb + swsum * pqbv[p]) * scale; sCB[p] = cb; }
    }
    __syncthreads();

    // ---- Stage 4: top-4 + softmax over the 4 ----
    if (warp == 0) {
        float s = 0.5f * sNB[lane] + 0.5f * sCB[lane];
        float vals[4]; int ids[4];
        #pragma unroll
        for (int r = 0; r < 4; r++) {
            float v = s; int idx = lane;
            #pragma unroll
            for (int o = 16; o > 0; o >>= 1) {
                float ov = __shfl_xor_sync(0xffffffffu, v, o);
                int   oi = __shfl_xor_sync(0xffffffffu, idx, o);
                if (ov > v || (ov == v && oi < idx)) { v = ov; idx = oi; }
            }
            vals[r] = v; ids[r] = idx;
            if (lane == idx) s = -3.4e38f;
        }
        if (lane == 0) {
            float m = fmaxf(fmaxf(vals[0], vals[1]), fmaxf(vals[2], vals[3]));
            float e0 = expf(vals[0] - m), e1 = expf(vals[1] - m);
            float e2 = expf(vals[2] - m), e3 = expf(vals[3] - m);
            float inv = 1.0f / (e0 + e1 + e2 + e3);
            sTw[0] = e0 * inv; sTw[1] = e1 * inv; sTw[2] = e2 * inv; sTw[3] = e3 * inv;
            sTi[0] = ids[0]; sTi[1] = ids[1]; sTi[2] = ids[2]; sTi[3] = ids[3];
        }
    }
    __syncthreads();

    // ---- Stage 5: selected nps rows, softmax, weight ----
    if (warp < 4) {
        int pi = sTi[warp];
        const float* PVp = PV + (size_t)pi * 1024;
        float pvr[32];
        #pragma unroll
        for (int u = 0; u < 32; u++) pvr[u] = PVp[u * 32 + lane];
        float sel[8];
        #pragma unroll
        for (int k = 0; k < 8; k++) {
            float a = 0.0f;
            #pragma unroll
            for (int u = 0; u < 32; u++)
                a = fmaf(pvr[u], sMix[k * 1028 + u * 32 + lane], a);
            #pragma unroll
            for (int o = 16; o > 0; o >>= 1) a += __shfl_xor_sync(0xffffffffu, a, o);
            sel[k] = a;
        }
        if (lane == 0) {
            float pb = pqbv[pi];
            #pragma unroll
            for (int k = 0; k < 8; k++) sel[k] = (sel[k] + pb) * scale;
            float m = sel[0];
            #pragma unroll
            for (int k = 1; k < 8; k++) m = fmaxf(m, sel[k]);
            float e[8], sum = 0.0f;
            #pragma unroll
            for (int k = 0; k < 8; k++) { e[k] = expf(sel[k] - m); sum += e[k]; }
            float f = sTw[warp] / sum;
            #pragma unroll
            for (int k = 0; k < 8; k++) sSel[warp][k] = e[k] * f;
        }
    }
    __syncthreads();
    if (t < 8) sFA[t] = sSel[0][t] + sSel[1][t] + sSel[2][t] + sSel[3][t];
    __syncthreads();

    // ---- Stage 6: agg_mix (tf32-rounded) + sfa ----
    float fa[8];
    #pragma unroll
    for (int k = 0; k < 8; k++) fa[k] = sFA[k];
    if (t == 0)
        sfaout[tok] = fa[0] + fa[1] + fa[2] + fa[3] + fa[4] + fa[5] + fa[6] + fa[7];
    #pragma unroll
    for (int r = 0; r < 4; r++) {
        int d = t + 256 * r;
        float a = 0.0f;
        #pragma unroll
        for (int k = 0; k < 8; k++) a = fmaf(fa[k], sMix[k * 1028 + d], a);
        aggmix[(size_t)tok * 1024 + d] = to_tf32(a);
    }
}

// ----------------------------------------------------------------------------
// Launch
// ----------------------------------------------------------------------------
extern "C" void kernel_launch(void* const* d_in, const int* in_sizes, int n_in,
                              void* d_out, int out_size)
{
    const float* x     = (const float*)d_in[0];
    const float* tw    = (const float*)d_in[3];
    const float* sn    = (const float*)d_in[4];
    const float* ctx   = (const float*)d_in[5];
    const float* Wq    = (const float*)d_in[6];
    const float* bq    = (const float*)d_in[7];
    const float* Wk    = (const float*)d_in[8];
    const float* bk    = (const float*)d_in[9];
    const float* Wv    = (const float*)d_in[10];
    const float* bv    = (const float*)d_in[11];
    const float* pq    = (const float*)d_in[12];
    const float* Wup   = (const float*)d_in[13];
    const float* bup   = (const float*)d_in[14];
    const float* Wdown = (const float*)d_in[15];
    const float* bdown = (const float*)d_in[16];
    float* out = (float*)d_out;

    float *Up, *comb, *h, *aggmix, *sfa, *Wqt, *Wkt, *Mt, *Wvr, *Wupr, *Wdnr;
    float *PV, *vqk, *vkq, *pqbv, *c0, *zeros;
    cudaGetSymbolAddress((void**)&Up,     g_U);
    cudaGetSymbolAddress((void**)&comb,   g_comb);
    cudaGetSymbolAddress((void**)&h,      g_h);
    cudaGetSymbolAddress((void**)&aggmix, g_aggmix);
    cudaGetSymbolAddress((void**)&sfa,    g_sfa);
    cudaGetSymbolAddress((void**)&Wqt,    g_Wqt);
    cudaGetSymbolAddress((void**)&Wkt,    g_Wkt);
    cudaGetSymbolAddress((void**)&Mt,     g_Mt);
    cudaGetSymbolAddress((void**)&Wvr,    g_Wvr);
    cudaGetSymbolAddress((void**)&Wupr,   g_Wupr);
    cudaGetSymbolAddress((void**)&Wdnr,   g_Wdnr);
    cudaGetSymbolAddress((void**)&PV,     g_PV);
    cudaGetSymbolAddress((void**)&vqk,    g_vqk);
    cudaGetSymbolAddress((void**)&vkq,    g_vkq);
    cudaGetSymbolAddress((void**)&pqbv,   g_pqbv);
    cudaGetSymbolAddress((void**)&c0,     g_c0);
    cudaGetSymbolAddress((void**)&zeros,  g_zeros);

    cudaFuncSetAttribute(gemm_mma, cudaFuncAttributeMaxDynamicSharedMemorySize, DYN_SMEM);
    cudaFuncSetAttribute(attn_fused, cudaFuncAttributeMaxDynamicSharedMemorySize, ATTN_SMEM);

    // ---- prepass ----
    {
        dim3 tb(32, 8), tg(32, 32);
        transpose_rnd<<<tg, tb>>>(Wqt, Wq);
        transpose_rnd<<<tg, tb>>>(Wkt, Wk);
        int s4 = (Dd * Dd) / 4;
        round_k<<<(s4 + 255) / 256, 256>>>(Wvr, Wv, s4);
        int u4 = (DFFd * Dd) / 4;
        round_k<<<(u4 + 255) / 256, 256>>>(Wupr, Wup, u4);
        round_k<<<(u4 + 255) / 256, 256>>>(Wdnr, Wdown, u4);
        prep_bias<<<8, 256>>>(vqk, vkq, Wq, bk, Wk, bq);
        prep_small<<<33, 256>>>(pqbv, c0, pq, bv, bq, bk);
        prep_pv<<<dim3(4, 32), 256>>>(PV, pq, Wv);
    }

    // Mt = Wkt @ Wqt^T  [1024x1024, K=1024], rounded output
    gemm_mma<<<64, 256, DYN_SMEM>>>(Wkt, Dd, Wqt, zeros, Mt, Dd,
                                    Dd, 8, 8, 2, 0, nullptr, nullptr);

    // U = sn @ Mt^T  [32768x1024, K=1024], A rounded in-kernel, fp32 output
    gemm_mma<<<2048, 256, DYN_SMEM>>>(sn, Dd, Mt, zeros, Up, Dd,
                                      Dd, 8, 8, 0, 1, nullptr, nullptr);

    // fused attention -> agg_mix, sfa
    attn_fused<<<NTOK, 256, ATTN_SMEM>>>(Up, sn, pq, PV, ctx, tw,
                                         vqk, vkq, pqbv, c0, aggmix, sfa);

    // comb = x + agg_mix @ Wv^T + sfa*bv  (rounded)  [4096x1024, K=1024]
    gemm_mma<<<256, 256, DYN_SMEM>>>(aggmix, Dd, Wvr, bv, comb, Dd,
                                     Dd, 8, 16, 3, 0, x, sfa);

    // FFN up (+GELU, rounded): [4096x4096, K=1024]
    gemm_mma<<<1024, 256, DYN_SMEM>>>(comb, Dd, Wupr, bup, h, DFFd,
                                      Dd, 32, 8, 1, 0, nullptr, nullptr);

    // FFN down: [4096x1024, K=4096]
    gemm_mma<<<256, 256, DYN_SMEM>>>(h, DFFd, Wdnr, bdown, out, Dd,
                                     DFFd, 8, 16, 0, 0, nullptr, nullptr);
}

// round 5
// speedup vs baseline: 3.8089x; 1.0031x over previous
#include <cuda_runtime.h>
#include <cuda_fp16.h>
#include <math.h>
#include <stdint.h>

// Problem constants
#define Bb    2
#define Ss    2048
#define Kn    8
#define Dd    1024
#define DFFd  4096
#define NTOK  (Bb*Ss)        // 4096 tokens
#define MQKV  (NTOK*Kn)      // 32768 rows

// ----------------------------------------------------------------------------
// Scratch (static device globals; no runtime allocation)
// ----------------------------------------------------------------------------
__device__ __half g_sn_h[(size_t)MQKV * Dd];    // fp16 selected_neurons
__device__ __half g_U[(size_t)MQKV * Dd];       // sn @ Mt^T (fp16)
__device__ __half g_comb[(size_t)NTOK * Dd];
__device__ __half g_h[(size_t)NTOK * DFFd];
__device__ __half g_aggmix[(size_t)NTOK * Dd];
__device__ float  g_sfa[NTOK];
__device__ __half g_Wqt[(size_t)Dd * Dd];       // Wq^T fp16
__device__ __half g_Wkt[(size_t)Dd * Dd];       // Wk^T fp16
__device__ __half g_Mt[(size_t)Dd * Dd];        // Wk^T @ Wq  (fp16)
__device__ __half g_Wvh[(size_t)Dd * Dd];
__device__ __half g_Wuph[(size_t)DFFd * Dd];
__device__ __half g_Wdnh[(size_t)Dd * DFFd];
__device__ float  g_PV[32 * Dd];                // pq @ Wv (fp32)
__device__ float  g_vqk[Dd];                    // Wq^T bk
__device__ float  g_vkq[Dd];                    // Wk^T bq
__device__ float  g_pqbv[32];                   // pq_p . bv
__device__ float  g_c0[1];                      // bq . bk
__device__ float  g_zeros[Dd];                  // zero bias

// ----------------------------------------------------------------------------
// Helpers (baseline ISA: cp.async / ldmatrix / mma.sync)
// ----------------------------------------------------------------------------
__device__ __forceinline__ uint32_t smem_u32(const void* p) {
    uint32_t a;
    asm("{ .reg .u64 t; cvta.to.shared.u64 t, %1; cvt.u32.u64 %0, t; }" : "=r"(a) : "l"(p));
    return a;
}
#define SW128(o) ((o) ^ (((o) >> 3) & 0x70))

__device__ __forceinline__ void cpa16(uint32_t s, const void* g) {
    asm volatile("cp.async.cg.shared.global [%0], [%1], 16;" :: "r"(s), "l"(g));
}
__device__ __forceinline__ void cpa_commit() {
    asm volatile("cp.async.commit_group;" ::: "memory");
}
template <int N>
__device__ __forceinline__ void cpa_wait() {
    asm volatile("cp.async.wait_group %0;" :: "n"(N) : "memory");
}
__device__ __forceinline__ void ldsm4(uint32_t& r0, uint32_t& r1, uint32_t& r2, uint32_t& r3,
                                      uint32_t addr) {
    asm volatile("ldmatrix.sync.aligned.m8n8.x4.shared.b16 {%0,%1,%2,%3}, [%4];"
                 : "=r"(r0), "=r"(r1), "=r"(r2), "=r"(r3) : "r"(addr));
}
__device__ __forceinline__ void mma_f16(float* c, uint32_t a0, uint32_t a1, uint32_t a2,
                                        uint32_t a3, uint32_t b0, uint32_t b1) {
    asm volatile(
        "mma.sync.aligned.m16n8k16.row.col.f32.f16.f16.f32 "
        "{%0,%1,%2,%3}, {%4,%5,%6,%7}, {%8,%9}, {%0,%1,%2,%3};"
        : "+f"(c[0]), "+f"(c[1]), "+f"(c[2]), "+f"(c[3])
        : "r"(a0), "r"(a1), "r"(a2), "r"(a3), "r"(b0), "r"(b1));
}
__device__ __forceinline__ float gelu_exact(float v) {
    return 0.5f * v * (1.0f + erff(v * 0.70710678118654752440f));
}

// ----------------------------------------------------------------------------
// fp16 mma.sync GEMM:  C[M,N] = A[M,K] @ B[N,K]^T + epilogue   (fp32 accum)
// CTA 128x128, BK=64 halves (128B rows, SW128), 3-stage cp.async,
// 8 warps: wm = warp&3 (32 rows), wn = warp>>2 (64 cols).
// act: 0 = +bias; 1 = +bias,gelu; 3 = +xadd + sfa[row]*bias.
// out_half: 1 -> __half output, 0 -> float output.
// ----------------------------------------------------------------------------
#define STAGE_BYTES 32768
#define B_OFF       16384
#define DYN_SMEM    (3 * STAGE_BYTES)

__global__ __launch_bounds__(256, 2) void gemm_h(
    const __half* __restrict__ A, int lda,
    const __half* __restrict__ Bw,
    const float* __restrict__ bias,
    void* __restrict__ Cout, int ldc,
    int Kd, int Nt, int band_m, int act, int out_half,
    const float* __restrict__ xadd, const float* __restrict__ sfa)
{
    extern __shared__ __align__(128) char dsm[];
    const uint32_t sbase = smem_u32(dsm);

    const int t    = threadIdx.x;
    const int warp = t >> 5;
    const int lane = t & 31;

    const int tpb  = band_m * Nt;
    const int band = blockIdx.x / tpb;
    const int rem  = blockIdx.x % tpb;
    const int m0   = (band * band_m + rem % band_m) * 128;
    const int n0   = (rem / band_m) * 128;

    const int wm0 = (warp & 3) * 32;
    const int wn0 = (warp >> 2) * 64;

    float acc[64];
    #pragma unroll
    for (int i = 0; i < 64; i++) acc[i] = 0.0f;

    const int NIT = Kd >> 6;

    auto load_stage = [&](int sl, int kIt) {
        const int k0 = kIt << 6;
        const uint32_t sb = sbase + sl * STAGE_BYTES;
        #pragma unroll
        for (int i = 0; i < 4; i++) {
            int gi = t + 256 * i;
            int row = gi >> 3, g = gi & 7;
            cpa16(sb + SW128((uint32_t)(row * 128 + g * 16)),
                  A + (size_t)(m0 + row) * lda + k0 + g * 8);
        }
        #pragma unroll
        for (int i = 0; i < 4; i++) {
            int gi = t + 256 * i;
            int row = gi >> 3, g = gi & 7;
            cpa16(sb + B_OFF + SW128((uint32_t)(row * 128 + g * 16)),
                  Bw + (size_t)(n0 + row) * Kd + k0 + g * 8);
        }
        cpa_commit();
    };

    load_stage(0, 0);
    load_stage(1, 1);

    for (int it = 0; it < NIT; it++) {
        if (it + 2 < NIT) load_stage((it + 2) % 3, it + 2);
        if (it + 2 < NIT)      cpa_wait<2>();
        else if (it + 1 < NIT) cpa_wait<1>();
        else                   cpa_wait<0>();
        __syncthreads();

        const uint32_t ab = sbase + (it % 3) * STAGE_BYTES;
        const uint32_t bb = ab + B_OFF;

        #pragma unroll
        for (int s = 0; s < 4; s++) {        // 4 x k16 per BK=64
            // A fragments: rows (lane&15), k-half (lane>>4)
            uint32_t a[2][4];
            #pragma unroll
            for (int mf = 0; mf < 2; mf++) {
                int row = wm0 + mf * 16 + (lane & 15);
                uint32_t off = (uint32_t)(row * 128 + s * 32 + ((lane >> 4) << 4));
                ldsm4(a[mf][0], a[mf][1], a[mf][2], a[mf][3], ab + SW128(off));
            }
            #pragma unroll
            for (int cp = 0; cp < 4; cp++) {
                uint32_t b0, b1, b2, b3;
                int nrow = wn0 + cp * 16 + ((lane >> 4) << 3) + (lane & 7);
                uint32_t off = (uint32_t)(nrow * 128 + s * 32 + (((lane >> 3) & 1) << 4));
                ldsm4(b0, b1, b2, b3, bb + SW128(off));
                #pragma unroll
                for (int mf = 0; mf < 2; mf++) {
                    mma_f16(&acc[(mf * 8 + cp * 2 + 0) * 4],
                            a[mf][0], a[mf][1], a[mf][2], a[mf][3], b0, b1);
                    mma_f16(&acc[(mf * 8 + cp * 2 + 1) * 4],
                            a[mf][0], a[mf][1], a[mf][2], a[mf][3], b2, b3);
                }
            }
        }
        __syncthreads();
    }

    // Epilogue
    const int gid = lane >> 2, ctg = lane & 3;
    float*  Cf = (float*)Cout;
    __half* Ch = (__half*)Cout;
    #pragma unroll
    for (int mf = 0; mf < 2; mf++) {
        int r0 = m0 + wm0 + mf * 16 + gid;
        float s0 = 0.0f, s1 = 0.0f;
        if (act == 3) { s0 = sfa[r0]; s1 = sfa[r0 + 8]; }
        #pragma unroll
        for (int nf = 0; nf < 8; nf++) {
            float* c = &acc[(mf * 8 + nf) * 4];
            int cc = n0 + wn0 + nf * 8 + ctg * 2;
            float2 bv2 = *(const float2*)(bias + cc);
            float v0 = c[0], v1 = c[1], v2 = c[2], v3 = c[3];
            if (act == 3) {
                float2 x0 = *(const float2*)(xadd + (size_t)r0 * ldc + cc);
                float2 x1 = *(const float2*)(xadd + (size_t)(r0 + 8) * ldc + cc);
                v0 += x0.x + s0 * bv2.x; v1 += x0.y + s0 * bv2.y;
                v2 += x1.x + s1 * bv2.x; v3 += x1.y + s1 * bv2.y;
            } else {
                v0 += bv2.x; v1 += bv2.y; v2 += bv2.x; v3 += bv2.y;
                if (act == 1) {
                    v0 = gelu_exact(v0); v1 = gelu_exact(v1);
                    v2 = gelu_exact(v2); v3 = gelu_exact(v3);
                }
            }
            if (out_half) {
                *(__half2*)(Ch + (size_t)r0 * ldc + cc)       = __floats2half2_rn(v0, v1);
                *(__half2*)(Ch + (size_t)(r0 + 8) * ldc + cc) = __floats2half2_rn(v2, v3);
            } else {
                float2 o0 = {v0, v1}, o1 = {v2, v3};
                *(float2*)(Cf + (size_t)r0 * ldc + cc) = o0;
                *(float2*)(Cf + (size_t)(r0 + 8) * ldc + cc) = o1;
            }
        }
    }
}

// ----------------------------------------------------------------------------
// Prepass kernels
// ----------------------------------------------------------------------------
__global__ void f2h_k(__half* __restrict__ d, const float* __restrict__ s, int n4) {
    int i = blockIdx.x * blockDim.x + threadIdx.x;
    if (i < n4) {
        float4 v = ((const float4*)s)[i];
        ((__half2*)d)[2 * i]     = __floats2half2_rn(v.x, v.y);
        ((__half2*)d)[2 * i + 1] = __floats2half2_rn(v.z, v.w);
    }
}
__global__ void transpose_h(__half* __restrict__ dst, const float* __restrict__ src) {
    __shared__ float tile[32][33];
    int bx = blockIdx.x * 32, by = blockIdx.y * 32;
    int tx = threadIdx.x, ty = threadIdx.y;
    #pragma unroll
    for (int r = 0; r < 32; r += 8)
        tile[ty + r][tx] = src[(size_t)(by + ty + r) * Dd + bx + tx];
    __syncthreads();
    #pragma unroll
    for (int r = 0; r < 32; r += 8)
        dst[(size_t)(bx + ty + r) * Dd + by + tx] = __float2half_rn(tile[tx][ty + r]);
}
__global__ void prep_bias(float* __restrict__ vqk, float* __restrict__ vkq,
                          const float* __restrict__ Wq, const float* __restrict__ bk,
                          const float* __restrict__ Wk, const float* __restrict__ bq) {
    int idx = blockIdx.x * blockDim.x + threadIdx.x;
    if (idx < Dd) {
        float a = 0.0f;
        for (int e = 0; e < Dd; e++) a = fmaf(Wq[(size_t)e * Dd + idx], bk[e], a);
        vqk[idx] = a;
    } else if (idx < 2 * Dd) {
        int d = idx - Dd;
        float a = 0.0f;
        for (int e = 0; e < Dd; e++) a = fmaf(Wk[(size_t)e * Dd + d], bq[e], a);
        vkq[d] = a;
    }
}
__global__ void prep_small(float* __restrict__ pqbv, float* __restrict__ c0,
                           const float* __restrict__ pq, const float* __restrict__ bv,
                           const float* __restrict__ bq, const float* __restrict__ bk) {
    __shared__ float red[256];
    int b = blockIdx.x, t = threadIdx.x;
    float a = 0.0f;
    if (b < 32) {
        for (int e = t; e < Dd; e += 256) a = fmaf(pq[(size_t)b * Dd + e], bv[e], a);
    } else {
        for (int e = t; e < Dd; e += 256) a = fmaf(bq[e], bk[e], a);
    }
    red[t] = a; __syncthreads();
    for (int o = 128; o > 0; o >>= 1) { if (t < o) red[t] += red[t + o]; __syncthreads(); }
    if (t == 0) { if (b < 32) pqbv[b] = red[0]; else c0[0] = red[0]; }
}
__global__ void prep_pv(float* __restrict__ PV, const float* __restrict__ pq,
                        const float* __restrict__ Wv) {
    int d = blockIdx.x * 256 + threadIdx.x;
    int p = blockIdx.y;
    float a = 0.0f;
    for (int e = 0; e < Dd; e++) a = fmaf(pq[(size_t)p * Dd + e], Wv[(size_t)e * Dd + d], a);
    PV[(size_t)p * Dd + d] = a;
}

// ----------------------------------------------------------------------------
// Fused per-token attention (factored). Reads U + sn (fp16); emits agg_mix(fp16)+sfa.
// ----------------------------------------------------------------------------
#define ATTN_SMEM ((8 * 1028 * 2 + 1028 + 1024) * 4)

__global__ __launch_bounds__(256) void attn_fused(
    const __half* __restrict__ U, const __half* __restrict__ sn,
    const float* __restrict__ pq, const float* __restrict__ PV,
    const float* __restrict__ ctx, const float* __restrict__ tw,
    const float* __restrict__ vqk, const float* __restrict__ vkq,
    const float* __restrict__ pqbv, const float* __restrict__ c0p,
    __half* __restrict__ aggmix, float* __restrict__ sfaout)
{
    extern __shared__ float dynsm[];
    float* sSn   = dynsm;                 // 8*1028
    float* sMix  = sSn + 8 * 1028;        // 8*1028
    float* sWMix = sMix + 8 * 1028;       // 1028
    float* sCtx  = sWMix + 1028;          // 1024

    __shared__ float sA[8][8];
    __shared__ float sW[8], sTq[8], sTk[8];
    __shared__ float sNB[32], sCB[32];
    __shared__ float sSel[4][8];
    __shared__ float sTw[4];
    __shared__ int   sTi[4];
    __shared__ float sFA[8];
    __shared__ float sC0;

    const int tok  = blockIdx.x;
    const int t    = threadIdx.x;
    const int warp = t >> 5;
    const int lane = t & 31;
    const float scale = 0.03125f;

    const __half* snt = sn + (size_t)tok * 8 * 1024;
    const __half* Ut  = U + (size_t)tok * 8 * 1024;

    if (t < 8) sW[t] = tw[tok * 8 + t];
    if (t == 0) sC0 = c0p[0];
    #pragma unroll
    for (int r = 0; r < 16; r++) {
        int i2 = t + 256 * r;                  // half2 index (4096 total)
        __half2 v = ((const __half2*)snt)[i2];
        int d = i2 * 2;
        float* row = sSn + (d >> 10) * 1028 + (d & 1023);
        row[0] = __half2float(v.x); row[1] = __half2float(v.y);
    }
    #pragma unroll
    for (int r = 0; r < 4; r++) sCtx[t + 256 * r] = ctx[(size_t)tok * 1024 + t + 256 * r];
    __syncthreads();

    // ---- Stage 1: scores U_i . sn_j (+ bias corrections) ----
    float sc[8] = {0, 0, 0, 0, 0, 0, 0, 0};
    {
        const int i = warp;
        float tq = 0.0f, tk = 0.0f;
        for (int c = 0; c < 4; c++) {
            float uc[8];
            #pragma unroll
            for (int u = 0; u < 8; u++)
                uc[u] = __half2float(Ut[i * 1024 + c * 256 + u * 32 + lane]);
            #pragma unroll
            for (int j = 0; j < 8; j++) {
                float a = 0.0f;
                #pragma unroll
                for (int u = 0; u < 8; u++)
                    a = fmaf(uc[u], sSn[j * 1028 + c * 256 + u * 32 + lane], a);
                sc[j] += a;
            }
            #pragma unroll
            for (int u = 0; u < 8; u++) {
                int d = c * 256 + u * 32 + lane;
                float s = sSn[i * 1028 + d];
                tq = fmaf(s, vqk[d], tq);
                tk = fmaf(s, vkq[d], tk);
            }
        }
        #pragma unroll
        for (int j = 0; j < 8; j++) {
            float a = sc[j];
            #pragma unroll
            for (int o = 16; o > 0; o >>= 1) a += __shfl_xor_sync(0xffffffffu, a, o);
            sc[j] = a;
        }
        #pragma unroll
        for (int o = 16; o > 0; o >>= 1) {
            tq += __shfl_xor_sync(0xffffffffu, tq, o);
            tk += __shfl_xor_sync(0xffffffffu, tk, o);
        }
        if (lane == 0) { sTq[i] = tq; sTk[i] = tk; }
    }
    __syncthreads();
    {
        const int i = warp;
        float tqi = sTq[i], c0v = sC0;
        float f[8];
        #pragma unroll
        for (int j = 0; j < 8; j++) f[j] = (sc[j] + tqi + sTk[j] + c0v) * scale;
        if (lane == 0) {
            float m = f[0];
            #pragma unroll
            for (int j = 1; j < 8; j++) m = fmaxf(m, f[j]);
            float e[8], s = 0.0f;
            #pragma unroll
            for (int j = 0; j < 8; j++) { e[j] = expf(f[j] - m); s += e[j]; }
            float inv = 1.0f / s;
            #pragma unroll
            for (int j = 0; j < 8; j++) sA[i][j] = e[j] * inv;
        }
    }
    __syncthreads();

    // ---- Stage 2: mix = attn @ sn; wmix ----
    #pragma unroll
    for (int r = 0; r < 4; r++) {
        int d = t + 256 * r;
        float a[8] = {0,0,0,0,0,0,0,0};
        #pragma unroll
        for (int j = 0; j < 8; j++) {
            float s = sSn[j * 1028 + d];
            #pragma unroll
            for (int i = 0; i < 8; i++) a[i] = fmaf(sA[i][j], s, a[i]);
        }
        float wm = 0.0f;
        #pragma unroll
        for (int i = 0; i < 8; i++) { sMix[i * 1028 + d] = a[i]; wm = fmaf(sW[i], a[i], wm); }
        sWMix[d] = wm;
    }
    __syncthreads();

    // ---- Stage 3: neuron_based (PV) + context_based (pq) ----
    float swsum = sW[0] + sW[1] + sW[2] + sW[3] + sW[4] + sW[5] + sW[6] + sW[7];
    #pragma unroll
    for (int q = 0; q < 4; q++) {
        int p = warp * 4 + q;
        const float* PVp = PV + (size_t)p * 1024;
        const float* pqp = pq + (size_t)p * 1024;
        float nb = 0.0f, cb = 0.0f;
        #pragma unroll
        for (int u = 0; u < 32; u++) {
            int d = u * 32 + lane;
            nb = fmaf(PVp[d], sWMix[d], nb);
            cb = fmaf(pqp[d], sCtx[d], cb);
        }
        #pragma unroll
        for (int o = 16; o > 0; o >>= 1) {
            nb += __shfl_xor_sync(0xffffffffu, nb, o);
            cb += __shfl_xor_sync(0xffffffffu, cb, o);
        }
        if (lane == 0) { sNB[p] = (nb + swsum * pqbv[p]) * scale; sCB[p] = cb; }
    }
    __syncthreads();

    // ---- Stage 4: top-4 + softmax over the 4 ----
    if (warp == 0) {
        float s = 0.5f * sNB[lane] + 0.5f * sCB[lane];
        float vals[4]; int ids[4];
        #pragma unroll
        for (int r = 0; r < 4; r++) {
            float v = s; int idx = lane;
            #pragma unroll
            for (int o = 16; o > 0; o >>= 1) {
                float ov = __shfl_xor_sync(0xffffffffu, v, o);
                int   oi = __shfl_xor_sync(0xffffffffu, idx, o);
                if (ov > v || (ov == v && oi < idx)) { v = ov; idx = oi; }
            }
            vals[r] = v; ids[r] = idx;
            if (lane == idx) s = -3.4e38f;
        }
        if (lane == 0) {
            float m = fmaxf(fmaxf(vals[0], vals[1]), fmaxf(vals[2], vals[3]));
            float e0 = expf(vals[0] - m), e1 = expf(vals[1] - m);
            float e2 = expf(vals[2] - m), e3 = expf(vals[3] - m);
            float inv = 1.0f / (e0 + e1 + e2 + e3);
            sTw[0] = e0 * inv; sTw[1] = e1 * inv; sTw[2] = e2 * inv; sTw[3] = e3 * inv;
            sTi[0] = ids[0]; sTi[1] = ids[1]; sTi[2] = ids[2]; sTi[3] = ids[3];
        }
    }
    __syncthreads();

    // ---- Stage 5: selected nps rows, softmax, weight ----
    if (warp < 4) {
        int pi = sTi[warp];
        const float* PVp = PV + (size_t)pi * 1024;
        float pvr[32];
        #pragma unroll
        for (int u = 0; u < 32; u++) pvr[u] = PVp[u * 32 + lane];
        float sel[8];
        #pragma unroll
        for (int k = 0; k < 8; k++) {
            float a = 0.0f;
            #pragma unroll
            for (int u = 0; u < 32; u++)
                a = fmaf(pvr[u], sMix[k * 1028 + u * 32 + lane], a);
            #pragma unroll
            for (int o = 16; o > 0; o >>= 1) a += __shfl_xor_sync(0xffffffffu, a, o);
            sel[k] = a;
        }
        if (lane == 0) {
            float pb = pqbv[pi];
            #pragma unroll
            for (int k = 0; k < 8; k++) sel[k] = (sel[k] + pb) * scale;
            float m = sel[0];
            #pragma unroll
            for (int k = 1; k < 8; k++) m = fmaxf(m, sel[k]);
            float e[8], sum = 0.0f;
            #pragma unroll
            for (int k = 0; k < 8; k++) { e[k] = expf(sel[k] - m); sum += e[k]; }
            float f = sTw[warp] / sum;
            #pragma unroll
            for (int k = 0; k < 8; k++) sSel[warp][k] = e[k] * f;
        }
    }
    __syncthreads();
    if (t < 8) sFA[t] = sSel[0][t] + sSel[1][t] + sSel[2][t] + sSel[3][t];
    __syncthreads();

    // ---- Stage 6: agg_mix (fp16) + sfa ----
    float fa[8];
    #pragma unroll
    for (int k = 0; k < 8; k++) fa[k] = sFA[k];
    if (t == 0)
        sfaout[tok] = fa[0] + fa[1] + fa[2] + fa[3] + fa[4] + fa[5] + fa[6] + fa[7];
    #pragma unroll
    for (int r = 0; r < 4; r++) {
        int d = t + 256 * r;
        float a = 0.0f;
        #pragma unroll
        for (int k = 0; k < 8; k++) a = fmaf(fa[k], sMix[k * 1028 + d], a);
        aggmix[(size_t)tok * 1024 + d] = __float2half_rn(a);
    }
}

// ----------------------------------------------------------------------------
// Launch
// ----------------------------------------------------------------------------
extern "C" void kernel_launch(void* const* d_in, const int* in_sizes, int n_in,
                              void* d_out, int out_size)
{
    const float* x     = (const float*)d_in[0];
    const float* tw    = (const float*)d_in[3];
    const float* sn    = (const float*)d_in[4];
    const float* ctx   = (const float*)d_in[5];
    const float* Wq    = (const float*)d_in[6];
    const float* bq    = (const float*)d_in[7];
    const float* Wk    = (const float*)d_in[8];
    const float* bk    = (const float*)d_in[9];
    const float* Wv    = (const float*)d_in[10];
    const float* bv    = (const float*)d_in[11];
    const float* pq    = (const float*)d_in[12];
    const float* Wup   = (const float*)d_in[13];
    const float* bup   = (const float*)d_in[14];
    const float* Wdown = (const float*)d_in[15];
    const float* bdown = (const float*)d_in[16];
    float* out = (float*)d_out;

    __half *snh, *Up, *comb, *h, *aggmix, *Wqt, *Wkt, *Mt, *Wvh, *Wuph, *Wdnh;
    float *sfa, *PV, *vqk, *vkq, *pqbv, *c0, *zeros;
    cudaGetSymbolAddress((void**)&snh,    g_sn_h);
    cudaGetSymbolAddress((void**)&Up,     g_U);
    cudaGetSymbolAddress((void**)&comb,   g_comb);
    cudaGetSymbolAddress((void**)&h,      g_h);
    cudaGetSymbolAddress((void**)&aggmix, g_aggmix);
    cudaGetSymbolAddress((void**)&sfa,    g_sfa);
    cudaGetSymbolAddress((void**)&Wqt,    g_Wqt);
    cudaGetSymbolAddress((void**)&Wkt,    g_Wkt);
    cudaGetSymbolAddress((void**)&Mt,     g_Mt);
    cudaGetSymbolAddress((void**)&Wvh,    g_Wvh);
    cudaGetSymbolAddress((void**)&Wuph,   g_Wuph);
    cudaGetSymbolAddress((void**)&Wdnh,   g_Wdnh);
    cudaGetSymbolAddress((void**)&PV,     g_PV);
    cudaGetSymbolAddress((void**)&vqk,    g_vqk);
    cudaGetSymbolAddress((void**)&vkq,    g_vkq);
    cudaGetSymbolAddress((void**)&pqbv,   g_pqbv);
    cudaGetSymbolAddress((void**)&c0,     g_c0);
    cudaGetSymbolAddress((void**)&zeros,  g_zeros);

    cudaFuncSetAttribute(gemm_h, cudaFuncAttributeMaxDynamicSharedMemorySize, DYN_SMEM);
    cudaFuncSetAttribute(attn_fused, cudaFuncAttributeMaxDynamicSharedMemorySize, ATTN_SMEM);

    // ---- prepass: fp16 conversions + tiny fp32 precomputes ----
    {
        dim3 tb(32, 8), tg(32, 32);
        transpose_h<<<tg, tb>>>(Wqt, Wq);
        transpose_h<<<tg, tb>>>(Wkt, Wk);
        int n4 = (MQKV * Dd) / 4;
        f2h_k<<<(n4 + 255) / 256, 256>>>(snh, sn, n4);
        int s4 = (Dd * Dd) / 4;
        f2h_k<<<(s4 + 255) / 256, 256>>>(Wvh, Wv, s4);
        int u4 = (DFFd * Dd) / 4;
        f2h_k<<<(u4 + 255) / 256, 256>>>(Wuph, Wup, u4);
        f2h_k<<<(u4 + 255) / 256, 256>>>(Wdnh, Wdown, u4);
        prep_bias<<<8, 256>>>(vqk, vkq, Wq, bk, Wk, bq);
        prep_small<<<33, 256>>>(pqbv, c0, pq, bv, bq, bk);
        prep_pv<<<dim3(4, 32), 256>>>(PV, pq, Wv);
    }

    // Mt = Wkt @ Wqt^T  [1024x1024, K=1024] -> fp16
    gemm_h<<<64, 256, DYN_SMEM>>>(Wkt, Dd, Wqt, zeros, Mt, Dd,
                                  Dd, 8, 8, 0, 1, nullptr, nullptr);

    // U = sn_h @ Mt^T  [32768x1024, K=1024] -> fp16
    gemm_h<<<2048, 256, DYN_SMEM>>>(snh, Dd, Mt, zeros, Up, Dd,
                                    Dd, 8, 8, 0, 1, nullptr, nullptr);

    // fused attention -> agg_mix (fp16), sfa
    attn_fused<<<NTOK, 256, ATTN_SMEM>>>(Up, snh, pq, PV, ctx, tw,
                                         vqk, vkq, pqbv, c0, aggmix, sfa);

    // comb = x + agg_mix @ Wv^T + sfa*bv  [4096x1024, K=1024] -> fp16
    gemm_h<<<256, 256, DYN_SMEM>>>(aggmix, Dd, Wvh, bv, comb, Dd,
                                   Dd, 8, 16, 3, 1, x, sfa);

    // FFN up (+GELU): [4096x4096, K=1024] -> fp16
    gemm_h<<<1024, 256, DYN_SMEM>>>(comb, Dd, Wuph, bup, h, DFFd,
                                    Dd, 32, 8, 1, 1, nullptr, nullptr);

    // FFN down: [4096x1024, K=4096] -> fp32 output
    gemm_h<<<256, 256, DYN_SMEM>>>(h, DFFd, Wdnh, bdown, out, Dd,
                                   DFFd, 8, 16, 0, 0, nullptr, nullptr);
}

// round 6
// speedup vs baseline: 4.5625x; 1.1978x over previous
#include <cuda_runtime.h>
#include <cuda_fp16.h>
#include <math.h>
#include <stdint.h>

// Problem constants
#define Bb    2
#define Ss    2048
#define Kn    8
#define Dd    1024
#define DFFd  4096
#define NTOK  (Bb*Ss)        // 4096 tokens
#define MQKV  (NTOK*Kn)      // 32768 rows

// ----------------------------------------------------------------------------
// Scratch (static device globals; no runtime allocation)
// ----------------------------------------------------------------------------
__device__ __half g_sn_h[(size_t)MQKV * Dd];    // fp16 selected_neurons
__device__ __half g_U[(size_t)MQKV * Dd];       // sn @ Mt^T (fp16)
__device__ __half g_comb[(size_t)NTOK * Dd];
__device__ __half g_h[(size_t)NTOK * DFFd];
__device__ __half g_aggmix[(size_t)NTOK * Dd];
__device__ float  g_sfa[NTOK];
__device__ __half g_Wqt[(size_t)Dd * Dd];       // Wq^T fp16
__device__ __half g_Wkt[(size_t)Dd * Dd];       // Wk^T fp16
__device__ __half g_Mt[(size_t)Dd * Dd];        // Wk^T @ Wq  (fp16)
__device__ __half g_Wvh[(size_t)Dd * Dd];
__device__ __half g_Wuph[(size_t)DFFd * Dd];
__device__ __half g_Wdnh[(size_t)Dd * DFFd];
__device__ float  g_PV[32 * Dd];                // pq @ Wv (fp32)
__device__ float  g_vqk[Dd];                    // Wq^T bk
__device__ float  g_vkq[Dd];                    // Wk^T bq
__device__ float  g_pqbv[32];                   // pq_p . bv
__device__ float  g_c0[1];                      // bq . bk
__device__ float  g_zeros[Dd];                  // zero bias

// ----------------------------------------------------------------------------
// Helpers (baseline ISA: cp.async / ldmatrix / mma.sync)
// ----------------------------------------------------------------------------
__device__ __forceinline__ uint32_t smem_u32(const void* p) {
    uint32_t a;
    asm("{ .reg .u64 t; cvta.to.shared.u64 t, %1; cvt.u32.u64 %0, t; }" : "=r"(a) : "l"(p));
    return a;
}
#define SW128(o) ((o) ^ (((o) >> 3) & 0x70))

__device__ __forceinline__ void cpa16(uint32_t s, const void* g) {
    asm volatile("cp.async.cg.shared.global [%0], [%1], 16;" :: "r"(s), "l"(g));
}
__device__ __forceinline__ void cpa_commit() {
    asm volatile("cp.async.commit_group;" ::: "memory");
}
template <int N>
__device__ __forceinline__ void cpa_wait() {
    asm volatile("cp.async.wait_group %0;" :: "n"(N) : "memory");
}
__device__ __forceinline__ void ldsm4(uint32_t& r0, uint32_t& r1, uint32_t& r2, uint32_t& r3,
                                      uint32_t addr) {
    asm volatile("ldmatrix.sync.aligned.m8n8.x4.shared.b16 {%0,%1,%2,%3}, [%4];"
                 : "=r"(r0), "=r"(r1), "=r"(r2), "=r"(r3) : "r"(addr));
}
// fp32-accumulator fp16 mma
__device__ __forceinline__ void mma_f16(float* c, uint32_t a0, uint32_t a1, uint32_t a2,
                                        uint32_t a3, uint32_t b0, uint32_t b1) {
    asm volatile(
        "mma.sync.aligned.m16n8k16.row.col.f32.f16.f16.f32 "
        "{%0,%1,%2,%3}, {%4,%5,%6,%7}, {%8,%9}, {%0,%1,%2,%3};"
        : "+f"(c[0]), "+f"(c[1]), "+f"(c[2]), "+f"(c[3])
        : "r"(a0), "r"(a1), "r"(a2), "r"(a3), "r"(b0), "r"(b1));
}
// fp16-accumulator fp16 mma, zero accumulator in (one f16 rounding per 16-term dot)
__device__ __forceinline__ void mma_f16h0(uint32_t& d0, uint32_t& d1,
                                          uint32_t a0, uint32_t a1, uint32_t a2, uint32_t a3,
                                          uint32_t b0, uint32_t b1) {
    asm volatile(
        "mma.sync.aligned.m16n8k16.row.col.f16.f16.f16.f16 "
        "{%0,%1}, {%2,%3,%4,%5}, {%6,%7}, {%8,%8};"
        : "=r"(d0), "=r"(d1)
        : "r"(a0), "r"(a1), "r"(a2), "r"(a3), "r"(b0), "r"(b1), "r"(0u));
}
__device__ __forceinline__ void hacc_add(float* c, uint32_t d0, uint32_t d1) {
    float2 lo = __half22float2(*(__half2*)&d0);
    float2 hi = __half22float2(*(__half2*)&d1);
    c[0] += lo.x; c[1] += lo.y; c[2] += hi.x; c[3] += hi.y;
}
__device__ __forceinline__ float gelu_exact(float v) {
    return 0.5f * v * (1.0f + erff(v * 0.70710678118654752440f));
}

// ----------------------------------------------------------------------------
// fp16 mma.sync GEMM:  C[M,N] = A[M,K] @ B[N,K]^T + epilogue
// CTA 128x128, BK=64, 3-stage cp.async, SW128, 8 warps (4M x 2N), 32x64 warp tile.
// acc16: 1 -> f16-accumulate per mma + f32 master accumulation (2x rate if gated)
// act: 0 = +bias; 1 = +bias,gelu; 3 = +xadd + sfa[row]*bias.
// out_half: 1 -> __half output, 0 -> float output.
// ----------------------------------------------------------------------------
#define STAGE_BYTES 32768
#define B_OFF       16384
#define DYN_SMEM    (3 * STAGE_BYTES)

__global__ __launch_bounds__(256, 2) void gemm_h(
    const __half* __restrict__ A, int lda,
    const __half* __restrict__ Bw,
    const float* __restrict__ bias,
    void* __restrict__ Cout, int ldc,
    int Kd, int Nt, int band_m, int act, int out_half, int acc16,
    const float* __restrict__ xadd, const float* __restrict__ sfa)
{
    extern __shared__ __align__(128) char dsm[];
    const uint32_t sbase = smem_u32(dsm);

    const int t    = threadIdx.x;
    const int warp = t >> 5;
    const int lane = t & 31;

    const int tpb  = band_m * Nt;
    const int band = blockIdx.x / tpb;
    const int rem  = blockIdx.x % tpb;
    const int m0   = (band * band_m + rem % band_m) * 128;
    const int n0   = (rem / band_m) * 128;

    const int wm0 = (warp & 3) * 32;
    const int wn0 = (warp >> 2) * 64;

    float acc[64];
    #pragma unroll
    for (int i = 0; i < 64; i++) acc[i] = 0.0f;

    const int NIT = Kd >> 6;

    auto load_stage = [&](int sl, int kIt) {
        const int k0 = kIt << 6;
        const uint32_t sb = sbase + sl * STAGE_BYTES;
        #pragma unroll
        for (int i = 0; i < 4; i++) {
            int gi = t + 256 * i;
            int row = gi >> 3, g = gi & 7;
            cpa16(sb + SW128((uint32_t)(row * 128 + g * 16)),
                  A + (size_t)(m0 + row) * lda + k0 + g * 8);
        }
        #pragma unroll
        for (int i = 0; i < 4; i++) {
            int gi = t + 256 * i;
            int row = gi >> 3, g = gi & 7;
            cpa16(sb + B_OFF + SW128((uint32_t)(row * 128 + g * 16)),
                  Bw + (size_t)(n0 + row) * Kd + k0 + g * 8);
        }
        cpa_commit();
    };

    load_stage(0, 0);
    load_stage(1, 1);

    for (int it = 0; it < NIT; it++) {
        if (it + 2 < NIT) load_stage((it + 2) % 3, it + 2);
        if (it + 2 < NIT)      cpa_wait<2>();
        else if (it + 1 < NIT) cpa_wait<1>();
        else                   cpa_wait<0>();
        __syncthreads();

        const uint32_t ab = sbase + (it % 3) * STAGE_BYTES;
        const uint32_t bb = ab + B_OFF;

        #pragma unroll
        for (int s = 0; s < 4; s++) {        // 4 x k16 per BK=64
            uint32_t a[2][4];
            #pragma unroll
            for (int mf = 0; mf < 2; mf++) {
                int row = wm0 + mf * 16 + (lane & 15);
                uint32_t off = (uint32_t)(row * 128 + s * 32 + ((lane >> 4) << 4));
                ldsm4(a[mf][0], a[mf][1], a[mf][2], a[mf][3], ab + SW128(off));
            }
            #pragma unroll
            for (int cp = 0; cp < 4; cp++) {
                uint32_t b0, b1, b2, b3;
                int nrow = wn0 + cp * 16 + ((lane >> 4) << 3) + (lane & 7);
                uint32_t off = (uint32_t)(nrow * 128 + s * 32 + (((lane >> 3) & 1) << 4));
                ldsm4(b0, b1, b2, b3, bb + SW128(off));
                if (acc16) {
                    #pragma unroll
                    for (int mf = 0; mf < 2; mf++) {
                        uint32_t d0, d1, d2, d3;
                        mma_f16h0(d0, d1, a[mf][0], a[mf][1], a[mf][2], a[mf][3], b0, b1);
                        mma_f16h0(d2, d3, a[mf][0], a[mf][1], a[mf][2], a[mf][3], b2, b3);
                        hacc_add(&acc[(mf * 8 + cp * 2 + 0) * 4], d0, d1);
                        hacc_add(&acc[(mf * 8 + cp * 2 + 1) * 4], d2, d3);
                    }
                } else {
                    #pragma unroll
                    for (int mf = 0; mf < 2; mf++) {
                        mma_f16(&acc[(mf * 8 + cp * 2 + 0) * 4],
                                a[mf][0], a[mf][1], a[mf][2], a[mf][3], b0, b1);
                        mma_f16(&acc[(mf * 8 + cp * 2 + 1) * 4],
                                a[mf][0], a[mf][1], a[mf][2], a[mf][3], b2, b3);
                    }
                }
            }
        }
        __syncthreads();
    }

    // Epilogue
    const int gid = lane >> 2, ctg = lane & 3;
    float*  Cf = (float*)Cout;
    __half* Ch = (__half*)Cout;
    #pragma unroll
    for (int mf = 0; mf < 2; mf++) {
        int r0 = m0 + wm0 + mf * 16 + gid;
        float s0 = 0.0f, s1 = 0.0f;
        if (act == 3) { s0 = sfa[r0]; s1 = sfa[r0 + 8]; }
        #pragma unroll
        for (int nf = 0; nf < 8; nf++) {
            float* c = &acc[(mf * 8 + nf) * 4];
            int cc = n0 + wn0 + nf * 8 + ctg * 2;
            float2 bv2 = *(const float2*)(bias + cc);
            float v0 = c[0], v1 = c[1], v2 = c[2], v3 = c[3];
            if (act == 3) {
                float2 x0 = *(const float2*)(xadd + (size_t)r0 * ldc + cc);
                float2 x1 = *(const float2*)(xadd + (size_t)(r0 + 8) * ldc + cc);
                v0 += x0.x + s0 * bv2.x; v1 += x0.y + s0 * bv2.y;
                v2 += x1.x + s1 * bv2.x; v3 += x1.y + s1 * bv2.y;
            } else {
                v0 += bv2.x; v1 += bv2.y; v2 += bv2.x; v3 += bv2.y;
                if (act == 1) {
                    v0 = gelu_exact(v0); v1 = gelu_exact(v1);
                    v2 = gelu_exact(v2); v3 = gelu_exact(v3);
                }
            }
            if (out_half) {
                *(__half2*)(Ch + (size_t)r0 * ldc + cc)       = __floats2half2_rn(v0, v1);
                *(__half2*)(Ch + (size_t)(r0 + 8) * ldc + cc) = __floats2half2_rn(v2, v3);
            } else {
                float2 o0 = {v0, v1}, o1 = {v2, v3};
                *(float2*)(Cf + (size_t)r0 * ldc + cc) = o0;
                *(float2*)(Cf + (size_t)(r0 + 8) * ldc + cc) = o1;
            }
        }
    }
}

// ----------------------------------------------------------------------------
// Prepass kernels
// ----------------------------------------------------------------------------
__global__ void f2h_k(__half* __restrict__ d, const float* __restrict__ s, int n4) {
    int i = blockIdx.x * blockDim.x + threadIdx.x;
    if (i < n4) {
        float4 v = ((const float4*)s)[i];
        ((__half2*)d)[2 * i]     = __floats2half2_rn(v.x, v.y);
        ((__half2*)d)[2 * i + 1] = __floats2half2_rn(v.z, v.w);
    }
}
__global__ void transpose_h(__half* __restrict__ dst, const float* __restrict__ src) {
    __shared__ float tile[32][33];
    int bx = blockIdx.x * 32, by = blockIdx.y * 32;
    int tx = threadIdx.x, ty = threadIdx.y;
    #pragma unroll
    for (int r = 0; r < 32; r += 8)
        tile[ty + r][tx] = src[(size_t)(by + ty + r) * Dd + bx + tx];
    __syncthreads();
    #pragma unroll
    for (int r = 0; r < 32; r += 8)
        dst[(size_t)(bx + ty + r) * Dd + by + tx] = __float2half_rn(tile[tx][ty + r]);
}
__global__ void prep_bias(float* __restrict__ vqk, float* __restrict__ vkq,
                          const float* __restrict__ Wq, const float* __restrict__ bk,
                          const float* __restrict__ Wk, const float* __restrict__ bq) {
    int idx = blockIdx.x * blockDim.x + threadIdx.x;
    if (idx < Dd) {
        float a = 0.0f;
        for (int e = 0; e < Dd; e++) a = fmaf(Wq[(size_t)e * Dd + idx], bk[e], a);
        vqk[idx] = a;
    } else if (idx < 2 * Dd) {
        int d = idx - Dd;
        float a = 0.0f;
        for (int e = 0; e < Dd; e++) a = fmaf(Wk[(size_t)e * Dd + d], bq[e], a);
        vkq[d] = a;
    }
}
__global__ void prep_small(float* __restrict__ pqbv, float* __restrict__ c0,
                           const float* __restrict__ pq, const float* __restrict__ bv,
                           const float* __restrict__ bq, const float* __restrict__ bk) {
    __shared__ float red[256];
    int b = blockIdx.x, t = threadIdx.x;
    float a = 0.0f;
    if (b < 32) {
        for (int e = t; e < Dd; e += 256) a = fmaf(pq[(size_t)b * Dd + e], bv[e], a);
    } else {
        for (int e = t; e < Dd; e += 256) a = fmaf(bq[e], bk[e], a);
    }
    red[t] = a; __syncthreads();
    for (int o = 128; o > 0; o >>= 1) { if (t < o) red[t] += red[t + o]; __syncthreads(); }
    if (t == 0) { if (b < 32) pqbv[b] = red[0]; else c0[0] = red[0]; }
}
__global__ void prep_pv(float* __restrict__ PV, const float* __restrict__ pq,
                        const float* __restrict__ Wv) {
    int d = blockIdx.x * 256 + threadIdx.x;
    int p = blockIdx.y;
    float a = 0.0f;
    for (int e = 0; e < Dd; e++) a = fmaf(pq[(size_t)p * Dd + e], Wv[(size_t)e * Dd + d], a);
    PV[(size_t)p * Dd + d] = a;
}

// ----------------------------------------------------------------------------
// Fused per-token attention (factored). Reads U + sn (fp16); emits agg_mix(fp16)+sfa.
// ----------------------------------------------------------------------------
#define ATTN_SMEM ((8 * 1028 * 2 + 1028 + 1024) * 4)

__global__ __launch_bounds__(256) void attn_fused(
    const __half* __restrict__ U, const __half* __restrict__ sn,
    const float* __restrict__ pq, const float* __restrict__ PV,
    const float* __restrict__ ctx, const float* __restrict__ tw,
    const float* __restrict__ vqk, const float* __restrict__ vkq,
    const float* __restrict__ pqbv, const float* __restrict__ c0p,
    __half* __restrict__ aggmix, float* __restrict__ sfaout)
{
    extern __shared__ float dynsm[];
    float* sSn   = dynsm;
    float* sMix  = sSn + 8 * 1028;
    float* sWMix = sMix + 8 * 1028;
    float* sCtx  = sWMix + 1028;

    __shared__ float sA[8][8];
    __shared__ float sW[8], sTq[8], sTk[8];
    __shared__ float sNB[32], sCB[32];
    __shared__ float sSel[4][8];
    __shared__ float sTw[4];
    __shared__ int   sTi[4];
    __shared__ float sFA[8];
    __shared__ float sC0;

    const int tok  = blockIdx.x;
    const int t    = threadIdx.x;
    const int warp = t >> 5;
    const int lane = t & 31;
    const float scale = 0.03125f;

    const __half* snt = sn + (size_t)tok * 8 * 1024;
    const __half* Ut  = U + (size_t)tok * 8 * 1024;

    if (t < 8) sW[t] = tw[tok * 8 + t];
    if (t == 0) sC0 = c0p[0];
    #pragma unroll
    for (int r = 0; r < 16; r++) {
        int i2 = t + 256 * r;
        __half2 v = ((const __half2*)snt)[i2];
        int d = i2 * 2;
        float* row = sSn + (d >> 10) * 1028 + (d & 1023);
        row[0] = __half2float(v.x); row[1] = __half2float(v.y);
    }
    #pragma unroll
    for (int r = 0; r < 4; r++) sCtx[t + 256 * r] = ctx[(size_t)tok * 1024 + t + 256 * r];
    __syncthreads();

    float sc[8] = {0, 0, 0, 0, 0, 0, 0, 0};
    {
        const int i = warp;
        float tq = 0.0f, tk = 0.0f;
        for (int c = 0; c < 4; c++) {
            float uc[8];
            #pragma unroll
            for (int u = 0; u < 8; u++)
                uc[u] = __half2float(Ut[i * 1024 + c * 256 + u * 32 + lane]);
            #pragma unroll
            for (int j = 0; j < 8; j++) {
                float a = 0.0f;
                #pragma unroll
                for (int u = 0; u < 8; u++)
                    a = fmaf(uc[u], sSn[j * 1028 + c * 256 + u * 32 + lane], a);
                sc[j] += a;
            }
            #pragma unroll
            for (int u = 0; u < 8; u++) {
                int d = c * 256 + u * 32 + lane;
                float s = sSn[i * 1028 + d];
                tq = fmaf(s, vqk[d], tq);
                tk = fmaf(s, vkq[d], tk);
            }
        }
        #pragma unroll
        for (int j = 0; j < 8; j++) {
            float a = sc[j];
            #pragma unroll
            for (int o = 16; o > 0; o >>= 1) a += __shfl_xor_sync(0xffffffffu, a, o);
            sc[j] = a;
        }
        #pragma unroll
        for (int o = 16; o > 0; o >>= 1) {
            tq += __shfl_xor_sync(0xffffffffu, tq, o);
            tk += __shfl_xor_sync(0xffffffffu, tk, o);
        }
        if (lane == 0) { sTq[i] = tq; sTk[i] = tk; }
    }
    __syncthreads();
    {
        const int i = warp;
        float tqi = sTq[i], c0v = sC0;
        float f[8];
        #pragma unroll
        for (int j = 0; j < 8; j++) f[j] = (sc[j] + tqi + sTk[j] + c0v) * scale;
        if (lane == 0) {
            float m = f[0];
            #pragma unroll
            for (int j = 1; j < 8; j++) m = fmaxf(m, f[j]);
            float e[8], s = 0.0f;
            #pragma unroll
            for (int j = 0; j < 8; j++) { e[j] = expf(f[j] - m); s += e[j]; }
            float inv = 1.0f / s;
            #pragma unroll
            for (int j = 0; j < 8; j++) sA[i][j] = e[j] * inv;
        }
    }
    __syncthreads();

    #pragma unroll
    for (int r = 0; r < 4; r++) {
        int d = t + 256 * r;
        float a[8] = {0,0,0,0,0,0,0,0};
        #pragma unroll
        for (int j = 0; j < 8; j++) {
            float s = sSn[j * 1028 + d];
            #pragma unroll
            for (int i = 0; i < 8; i++) a[i] = fmaf(sA[i][j], s, a[i]);
        }
        float wm = 0.0f;
        #pragma unroll
        for (int i = 0; i < 8; i++) { sMix[i * 1028 + d] = a[i]; wm = fmaf(sW[i], a[i], wm); }
        sWMix[d] = wm;
    }
    __syncthreads();

    float swsum = sW[0] + sW[1] + sW[2] + sW[3] + sW[4] + sW[5] + sW[6] + sW[7];
    #pragma unroll
    for (int q = 0; q < 4; q++) {
        int p = warp * 4 + q;
        const float* PVp = PV + (size_t)p * 1024;
        const float* pqp = pq + (size_t)p * 1024;
        float nb = 0.0f, cb = 0.0f;
        #pragma unroll
        for (int u = 0; u < 32; u++) {
            int d = u * 32 + lane;
            nb = fmaf(PVp[d], sWMix[d], nb);
            cb = fmaf(pqp[d], sCtx[d], cb);
        }
        #pragma unroll
        for (int o = 16; o > 0; o >>= 1) {
            nb += __shfl_xor_sync(0xffffffffu, nb, o);
            cb += __shfl_xor_sync(0xffffffffu, cb, o);
        }
        if (lane == 0) { sNB[p] = (nb + swsum * pqbv[p]) * scale; sCB[p] = cb; }
    }
    __syncthreads();

    if (warp == 0) {
        float s = 0.5f * sNB[lane] + 0.5f * sCB[lane];
        float vals[4]; int ids[4];
        #pragma unroll
        for (int r = 0; r < 4; r++) {
            float v = s; int idx = lane;
            #pragma unroll
            for (int o = 16; o > 0; o >>= 1) {
                float ov = __shfl_xor_sync(0xffffffffu, v, o);
                int   oi = __shfl_xor_sync(0xffffffffu, idx, o);
                if (ov > v || (ov == v && oi < idx)) { v = ov; idx = oi; }
            }
            vals[r] = v; ids[r] = idx;
            if (lane == idx) s = -3.4e38f;
        }
        if (lane == 0) {
            float m = fmaxf(fmaxf(vals[0], vals[1]), fmaxf(vals[2], vals[3]));
            float e0 = expf(vals[0] - m), e1 = expf(vals[1] - m);
            float e2 = expf(vals[2] - m), e3 = expf(vals[3] - m);
            float inv = 1.0f / (e0 + e1 + e2 + e3);
            sTw[0] = e0 * inv; sTw[1] = e1 * inv; sTw[2] = e2 * inv; sTw[3] = e3 * inv;
            sTi[0] = ids[0]; sTi[1] = ids[1]; sTi[2] = ids[2]; sTi[3] = ids[3];
        }
    }
    __syncthreads();

    if (warp < 4) {
        int pi = sTi[warp];
        const float* PVp = PV + (size_t)pi * 1024;
        float pvr[32];
        #pragma unroll
        for (int u = 0; u < 32; u++) pvr[u] = PVp[u * 32 + lane];
        float sel[8];
        #pragma unroll
        for (int k = 0; k < 8; k++) {
            float a = 0.0f;
            #pragma unroll
            for (int u = 0; u < 32; u++)
                a = fmaf(pvr[u], sMix[k * 1028 + u * 32 + lane], a);
            #pragma unroll
            for (int o = 16; o > 0; o >>= 1) a += __shfl_xor_sync(0xffffffffu, a, o);
            sel[k] = a;
        }
        if (lane == 0) {
            float pb = pqbv[pi];
            #pragma unroll
            for (int k = 0; k < 8; k++) sel[k] = (sel[k] + pb) * scale;
            float m = sel[0];
            #pragma unroll
            for (int k = 1; k < 8; k++) m = fmaxf(m, sel[k]);
            float e[8], sum = 0.0f;
            #pragma unroll
            for (int k = 0; k < 8; k++) { e[k] = expf(sel[k] - m); sum += e[k]; }
            float f = sTw[warp] / sum;
            #pragma unroll
            for (int k = 0; k < 8; k++) sSel[warp][k] = e[k] * f;
        }
    }
    __syncthreads();
    if (t < 8) sFA[t] = sSel[0][t] + sSel[1][t] + sSel[2][t] + sSel[3][t];
    __syncthreads();

    float fa[8];
    #pragma unroll
    for (int k = 0; k < 8; k++) fa[k] = sFA[k];
    if (t == 0)
        sfaout[tok] = fa[0] + fa[1] + fa[2] + fa[3] + fa[4] + fa[5] + fa[6] + fa[7];
    #pragma unroll
    for (int r = 0; r < 4; r++) {
        int d = t + 256 * r;
        float a = 0.0f;
        #pragma unroll
        for (int k = 0; k < 8; k++) a = fmaf(fa[k], sMix[k * 1028 + d], a);
        aggmix[(size_t)tok * 1024 + d] = __float2half_rn(a);
    }
}

// ----------------------------------------------------------------------------
// Launch (ordered so ncu -s 5 -c 1 captures the U GEMM as launch #6)
// ----------------------------------------------------------------------------
extern "C" void kernel_launch(void* const* d_in, const int* in_sizes, int n_in,
                              void* d_out, int out_size)
{
    const float* x     = (const float*)d_in[0];
    const float* tw    = (const float*)d_in[3];
    const float* sn    = (const float*)d_in[4];
    const float* ctx   = (const float*)d_in[5];
    const float* Wq    = (const float*)d_in[6];
    const float* bq    = (const float*)d_in[7];
    const float* Wk    = (const float*)d_in[8];
    const float* bk    = (const float*)d_in[9];
    const float* Wv    = (const float*)d_in[10];
    const float* bv    = (const float*)d_in[11];
    const float* pq    = (const float*)d_in[12];
    const float* Wup   = (const float*)d_in[13];
    const float* bup   = (const float*)d_in[14];
    const float* Wdown = (const float*)d_in[15];
    const float* bdown = (const float*)d_in[16];
    float* out = (float*)d_out;

    __half *snh, *Up, *comb, *h, *aggmix, *Wqt, *Wkt, *Mt, *Wvh, *Wuph, *Wdnh;
    float *sfa, *PV, *vqk, *vkq, *pqbv, *c0, *zeros;
    cudaGetSymbolAddress((void**)&snh,    g_sn_h);
    cudaGetSymbolAddress((void**)&Up,     g_U);
    cudaGetSymbolAddress((void**)&comb,   g_comb);
    cudaGetSymbolAddress((void**)&h,      g_h);
    cudaGetSymbolAddress((void**)&aggmix, g_aggmix);
    cudaGetSymbolAddress((void**)&sfa,    g_sfa);
    cudaGetSymbolAddress((void**)&Wqt,    g_Wqt);
    cudaGetSymbolAddress((void**)&Wkt,    g_Wkt);
    cudaGetSymbolAddress((void**)&Mt,     g_Mt);
    cudaGetSymbolAddress((void**)&Wvh,    g_Wvh);
    cudaGetSymbolAddress((void**)&Wuph,   g_Wuph);
    cudaGetSymbolAddress((void**)&Wdnh,   g_Wdnh);
    cudaGetSymbolAddress((void**)&PV,     g_PV);
    cudaGetSymbolAddress((void**)&vqk,    g_vqk);
    cudaGetSymbolAddress((void**)&vkq,    g_vkq);
    cudaGetSymbolAddress((void**)&pqbv,   g_pqbv);
    cudaGetSymbolAddress((void**)&c0,     g_c0);
    cudaGetSymbolAddress((void**)&zeros,  g_zeros);

    cudaFuncSetAttribute(gemm_h, cudaFuncAttributeMaxDynamicSharedMemorySize, DYN_SMEM);
    cudaFuncSetAttribute(attn_fused, cudaFuncAttributeMaxDynamicSharedMemorySize, ATTN_SMEM);

    dim3 tb(32, 8), tg(32, 32);
    // #1, #2: weight transposes
    transpose_h<<<tg, tb>>>(Wqt, Wq);
    transpose_h<<<tg, tb>>>(Wkt, Wk);
    // #3: sn -> fp16
    int n4 = (MQKV * Dd) / 4;
    f2h_k<<<(n4 + 255) / 256, 256>>>(snh, sn, n4);
    // #4: Mt = Wkt @ Wqt^T  (f32 accum; tiny)
    gemm_h<<<64, 256, DYN_SMEM>>>(Wkt, Dd, Wqt, zeros, Mt, Dd,
                                  Dd, 8, 8, 0, 1, 0, nullptr, nullptr);
    // #5: bias precompute (independent)
    prep_bias<<<8, 256>>>(vqk, vkq, Wq, bk, Wk, bq);
    // #6: U = sn_h @ Mt^T  -> fp16   [PROFILED LAUNCH]  (f16 accum)
    gemm_h<<<2048, 256, DYN_SMEM>>>(snh, Dd, Mt, zeros, Up, Dd,
                                    Dd, 8, 8, 0, 1, 1, nullptr, nullptr);

    // remaining prepass
    int s4 = (Dd * Dd) / 4;
    f2h_k<<<(s4 + 255) / 256, 256>>>(Wvh, Wv, s4);
    int u4 = (DFFd * Dd) / 4;
    f2h_k<<<(u4 + 255) / 256, 256>>>(Wuph, Wup, u4);
    f2h_k<<<(u4 + 255) / 256, 256>>>(Wdnh, Wdown, u4);
    prep_small<<<33, 256>>>(pqbv, c0, pq, bv, bq, bk);
    prep_pv<<<dim3(4, 32), 256>>>(PV, pq, Wv);

    // fused attention -> agg_mix (fp16), sfa
    attn_fused<<<NTOK, 256, ATTN_SMEM>>>(Up, snh, pq, PV, ctx, tw,
                                         vqk, vkq, pqbv, c0, aggmix, sfa);

    // comb = x + agg_mix @ Wv^T + sfa*bv   (f32 accum, small)
    gemm_h<<<256, 256, DYN_SMEM>>>(aggmix, Dd, Wvh, bv, comb, Dd,
                                   Dd, 8, 16, 3, 1, 0, x, sfa);

    // FFN up (+GELU)  (f16 accum)
    gemm_h<<<1024, 256, DYN_SMEM>>>(comb, Dd, Wuph, bup, h, DFFd,
                                    Dd, 32, 8, 1, 1, 1, nullptr, nullptr);

    // FFN down -> fp32 output  (f32 accum, protects final precision)
    gemm_h<<<256, 256, DYN_SMEM>>>(h, DFFd, Wdnh, bdown, out, Dd,
                                   DFFd, 8, 16, 0, 0, 0, nullptr, nullptr);
}